// round 9
// baseline (speedup 1.0000x reference)
#include <cuda_runtime.h>
#include <math.h>

typedef unsigned long long u64;

// Problem constants
#define Bn   4
#define Cn   64
#define Hn   128
#define Wn   128
#define HWn  (Hn * Wn)          // 16384
#define K2n  9

// Tiling
#define TH      8
#define TW      32
#define HALO_H  10
#define HALO_W  34
#define HALO_SZ (Cn * HALO_H * HALO_W)   // 21760 floats

// k_main smem sub-buffer sizes (floats)
#define BB_STRIDE 264                    // im2col / v row stride
#define BB_SZ     (72 * BB_STRIDE)       // 19008
#define WB2_STRIDE 160                   // duplicated weights: 8 blocks x (16+4 pad)
#define WB2_SZ    (72 * WB2_STRIDE)      // 11520
#define META_SZ   (256 * 10)             // 2560
#define SMEM_MAIN (HALO_SZ + BB_SZ + WB2_SZ + META_SZ)   // 54848 floats = 219392 B

// -------- device scratch --------
__device__ float g_fused[Bn * Cn * HWn];
__device__ float g_off[Bn * 2 * K2n * HWn];
__device__ float g_mod[Bn * K2n * HWn];
__device__ float g_wct[K2n * 64 * 64];       // WcT[k][c][oc]

// -------- f32x2 helpers --------
__device__ __forceinline__ u64 pack2(float lo, float hi) {
    u64 r; asm("mov.b64 %0, {%1, %2};" : "=l"(r) : "f"(lo), "f"(hi)); return r;
}
__device__ __forceinline__ float2 unpack2(u64 v) {
    float2 r; asm("mov.b64 {%0, %1}, %2;" : "=f"(r.x), "=f"(r.y) : "l"(v)); return r;
}
__device__ __forceinline__ void ffma2(u64& d, u64 a, u64 b) {
    asm("fma.rn.f32x2 %0, %1, %2, %0;" : "+l"(d) : "l"(a), "l"(b));
}
__device__ __forceinline__ u64 d2u_lo(double2 d) {
    return __double_as_longlong(d.x);
}
__device__ __forceinline__ u64 d2u_hi(double2 d) {
    return __double_as_longlong(d.y);
}

// ============================================================
// Kernel 0: transpose w_conv -> WcT[k][c][oc]
// ============================================================
__global__ void k_wct(const float* __restrict__ wconv) {
    int i = blockIdx.x * 256 + threadIdx.x;
    if (i < K2n * 64 * 64) {
        int oc = i & 63;
        int c  = (i >> 6) & 63;
        int k  = i >> 12;
        g_wct[i] = wconv[(oc * 64 + c) * 9 + k];
    }
}

// ============================================================
// Kernel 1: fused = 1x1 conv over concat(x, ref)  (128 -> 64)
// ============================================================
__global__ void __launch_bounds__(256) k_fused(
    const float* __restrict__ x, const float* __restrict__ ref,
    const float* __restrict__ wcd, const float* __restrict__ bcd)
{
    __shared__ float ws[128 * 65];
    int tid = threadIdx.x;
    for (int i = tid; i < 128 * 64; i += 256) {
        int co = i >> 7, ci = i & 127;
        ws[ci * 65 + co] = wcd[i];
    }
    __syncthreads();

    int pid = blockIdx.x * 256 + tid;
    int b = pid >> 14;
    int p = pid & (HWn - 1);

    float acc[64];
#pragma unroll
    for (int co = 0; co < 64; co++) acc[co] = bcd[co];

    const float* xb = x   + (size_t)b * Cn * HWn + p;
    const float* rb = ref + (size_t)b * Cn * HWn + p;

    for (int ci = 0; ci < 64; ci++) {
        float v = __ldg(xb + ci * HWn);
        const float* w = ws + ci * 65;
#pragma unroll
        for (int co = 0; co < 64; co++) acc[co] += v * w[co];
    }
    for (int ci = 0; ci < 64; ci++) {
        float v = __ldg(rb + ci * HWn);
        const float* w = ws + (64 + ci) * 65;
#pragma unroll
        for (int co = 0; co < 64; co++) acc[co] += v * w[co];
    }

    float* o = g_fused + (size_t)b * Cn * HWn + p;
#pragma unroll
    for (int co = 0; co < 64; co++) o[co * HWn] = acc[co];
}

// ============================================================
// Kernel 2: off (18ch) + mod (9ch, sigmoid), 3x3 conv pad 1
// ============================================================
__global__ void __launch_bounds__(256) k_offmod(
    const float* __restrict__ wp, const float* __restrict__ bp,
    const float* __restrict__ wm, const float* __restrict__ bm)
{
    extern __shared__ float sm[];
    float* fs  = sm;
    float* ws2 = sm + HALO_SZ;

    int tid = threadIdx.x;
    int b  = blockIdx.z;
    int h0 = blockIdx.y * TH;
    int w0 = blockIdx.x * TW;

    const float* fb = g_fused + (size_t)b * Cn * HWn;
    for (int i = tid; i < HALO_SZ; i += 256) {
        int ic = i / (HALO_H * HALO_W);
        int rr = (i / HALO_W) % HALO_H;
        int cc = i % HALO_W;
        int gh = h0 - 1 + rr, gw = w0 - 1 + cc;
        float v = 0.f;
        if (gh >= 0 && gh < Hn && gw >= 0 && gw < Wn)
            v = fb[ic * HWn + gh * Wn + gw];
        fs[i] = v;
    }
    for (int i = tid; i < 27 * 576; i += 256) {
        int o = i / 576, j = i - o * 576;
        float v = (o < 18) ? wp[o * 576 + j] : wm[(o - 18) * 576 + j];
        ws2[j * 28 + o] = v;
    }
    __syncthreads();

    int ly = tid >> 5, lx = tid & 31;
    int base = ly * HALO_W + lx;

    float acc[27];
#pragma unroll
    for (int o = 0; o < 27; o++) acc[o] = (o < 18) ? bp[o] : bm[o - 18];

    for (int ic = 0; ic < 64; ic++) {
        float u[9];
#pragma unroll
        for (int t = 0; t < 9; t++)
            u[t] = fs[ic * (HALO_H * HALO_W) + base + (t / 3) * HALO_W + (t % 3)];
#pragma unroll
        for (int t = 0; t < 9; t++) {
            const float* w = ws2 + (ic * 9 + t) * 28;
#pragma unroll
            for (int o = 0; o < 27; o++) acc[o] += u[t] * w[o];
        }
    }

    int h = h0 + ly, w = w0 + lx;
    int pix = h * Wn + w;
#pragma unroll
    for (int o = 0; o < 18; o++)
        g_off[((size_t)b * 18 + o) * HWn + pix] = acc[o];
#pragma unroll
    for (int o = 0; o < 9; o++)
        g_mod[((size_t)b * 9 + o) * HWn + pix] = 1.f / (1.f + expf(-acc[18 + o]));
}

// ============================================================
// Kernel 3: main — FFMA2 (f32x2) register-tiled GEMMs.
// Weights staged DUPLICATED: row layout = 8 blocks of 20 floats,
// block mw holds pairs (w,w) for m = mw*8..mw*8+7  -> conflict-free LDS.128.
// ============================================================
__global__ void __launch_bounds__(256, 1) k_main(
    const float* __restrict__ x, const float* __restrict__ wc,
    const float* __restrict__ bc, float* __restrict__ out)
{
    extern __shared__ float sm[];
    float* fs   = sm;                      // [64][10][34]
    float* bbuf = sm + HALO_SZ;            // [72][264] im2col (aliased vbuf)
    float* wbuf = bbuf + BB_SZ;            // [72][160] duplicated weights / WcT
    float* meta = wbuf + WB2_SZ;           // [256][10]
    float* vbuf = bbuf;

    int tid = threadIdx.x;
    int b  = blockIdx.z;
    int h0 = blockIdx.y * TH;
    int w0 = blockIdx.x * TW;

    int mw  = tid & 7;
    int nw  = tid >> 3;
    int mw8 = mw << 3;
    int p0  = ((nw >> 2) << 5) + ((nw & 3) << 3);

    // --- halo load ---
    const float* fb = g_fused + (size_t)b * Cn * HWn;
    for (int i = tid; i < HALO_SZ; i += 256) {
        int ic = i / (HALO_H * HALO_W);
        int rr = (i / HALO_W) % HALO_H;
        int cc = i % HALO_W;
        int gh = h0 - 1 + rr, gw = w0 - 1 + cc;
        float v = 0.f;
        if (gh >= 0 && gh < Hn && gw >= 0 && gw < Wn)
            v = fb[ic * HWn + gh * Wn + gw];
        fs[i] = v;
    }

    int ly = tid >> 5, lx = tid & 31;
    int h = h0 + ly, w = w0 + lx;
    int pix = h * Wn + w;
    int basep = ly * HALO_W + lx;
    const float* xb = x + (size_t)b * Cn * HWn;

    u64 oacc[8][4];
#pragma unroll
    for (int i = 0; i < 8; i++)
#pragma unroll
        for (int jj = 0; jj < 4; jj++) oacc[i][jj] = 0ull;

    for (int k = 0; k < 9; k++) {
        __syncthreads();

        // ---- sampling metadata for pixel `tid` ----
        {
            float offx = g_off[((size_t)b * 18 + k) * HWn + pix];
            float offy = g_off[((size_t)b * 18 + 9 + k) * HWn + pix];
            float modk = g_mod[((size_t)b * 9 + k) * HWn + pix];

            float px = (float)(h + 1) + offx + (float)(k / 3 - 1);
            float py = (float)(w + 1) + offy + (float)(k % 3 - 1);
            float fx = floorf(px), fy = floorf(py);
            float qltx = fminf(fmaxf(fx,       0.f), 129.f);
            float qlty = fminf(fmaxf(fy,       0.f), 129.f);
            float qrbx = fminf(fmaxf(fx + 1.f, 0.f), 129.f);
            float qrby = fminf(fmaxf(fy + 1.f, 0.f), 129.f);
            float sx = fminf(fmaxf(px, 0.f), 129.f);
            float sy = fminf(fmaxf(py, 0.f), 129.f);
            float glt = (1.f + qltx - sx) * (1.f + qlty - sy);
            float grb = (1.f - qrbx + sx) * (1.f - qrby + sy);
            float glb = (1.f + qltx - sx) * (1.f - qrby + sy);
            float grt = (1.f - qrbx + sx) * (1.f + qlty - sy);

            int ix0 = (int)qltx, iy0 = (int)qlty;
            int ix1 = (int)qrbx, iy1 = (int)qrby;
            bool vx0 = (ix0 >= 1 && ix0 <= 128), vy0 = (iy0 >= 1 && iy0 <= 128);
            bool vx1 = (ix1 >= 1 && ix1 <= 128), vy1 = (iy1 >= 1 && iy1 <= 128);
            bool v00 = vx0 && vy0, v11 = vx1 && vy1;
            bool v01 = vx0 && vy1, v10 = vx1 && vy0;
            int o00 = v00 ? ((ix0 - 1) * Wn + (iy0 - 1)) : 0;
            int o11 = v11 ? ((ix1 - 1) * Wn + (iy1 - 1)) : 0;
            int o01 = v01 ? ((ix0 - 1) * Wn + (iy1 - 1)) : 0;
            int o10 = v10 ? ((ix1 - 1) * Wn + (iy0 - 1)) : 0;

            float* mt = meta + tid * 10;
            mt[0] = v00 ? glt : 0.f;
            mt[1] = v11 ? grb : 0.f;
            mt[2] = v01 ? glb : 0.f;
            mt[3] = v10 ? grt : 0.f;
            mt[4] = __int_as_float(o00);
            mt[5] = __int_as_float(o11);
            mt[6] = __int_as_float(o01);
            mt[7] = __int_as_float(o10);
            mt[8] = modk;
        }

        // ---- GEMM1: conv accumulators (f32x2 pairs along pixels) ----
        u64 acc[8][4];
#pragma unroll
        for (int i = 0; i < 8; i++) {
            float bi = bc[(mw8 + i) * 9 + k];
#pragma unroll
            for (int jj = 0; jj < 4; jj++) acc[i][jj] = pack2(bi, bi);
        }

        for (int s = 0; s < 8; s++) {
            __syncthreads();

            // build im2col chunk: bbuf[r][p=tid]
            {
                int r = 0;
#pragma unroll
                for (int lic = 0; lic < 8; lic++) {
                    int icb = (s * 8 + lic) * (HALO_H * HALO_W) + basep;
#pragma unroll
                    for (int t = 0; t < 9; t++) {
                        bbuf[r * BB_STRIDE + tid] = fs[icb + (t / 3) * HALO_W + (t % 3)];
                        r++;
                    }
                }
            }
            // stage duplicated weights: pairs (w,w), 64-bit STS
            for (int i = tid; i < 64 * 72; i += 256) {
                int m = i / 72, r = i - m * 72;
                float wv = wc[((size_t)(m * 9 + k)) * 576 + s * 72 + r];
                *(u64*)(wbuf + r * WB2_STRIDE + (m >> 3) * 20 + ((m & 7) << 1))
                    = pack2(wv, wv);
            }
            __syncthreads();

#pragma unroll 4
            for (int r = 0; r < 72; r++) {
                const double2* wd = (const double2*)(wbuf + r * WB2_STRIDE + mw * 20);
                const double2* bd = (const double2*)(bbuf + r * BB_STRIDE + p0);
                double2 a01 = wd[0], a23 = wd[1], a45 = wd[2], a67 = wd[3];
                double2 bq0 = bd[0], bq1 = bd[1];
                u64 ap[8] = {d2u_lo(a01), d2u_hi(a01), d2u_lo(a23), d2u_hi(a23),
                             d2u_lo(a45), d2u_hi(a45), d2u_lo(a67), d2u_hi(a67)};
                u64 bp[4] = {d2u_lo(bq0), d2u_hi(bq0), d2u_lo(bq1), d2u_hi(bq1)};
#pragma unroll
                for (int i = 0; i < 8; i++)
#pragma unroll
                    for (int jj = 0; jj < 4; jj++)
                        ffma2(acc[i][jj], ap[i], bp[jj]);
            }
        }

        __syncthreads();   // bbuf/wbuf reads done -> safe to overwrite

        // stage WcT_k duplicated into wbuf: row c, 8 blocks of 20
        for (int i = tid; i < 4096; i += 256) {
            int c = i >> 6, m = i & 63;
            float wv = g_wct[k * 4096 + i];
            *(u64*)(wbuf + c * WB2_STRIDE + (m >> 3) * 20 + ((m & 7) << 1))
                = pack2(wv, wv);
        }

        // unpack conv accumulators for the epilogue
        float accf[8][8];
#pragma unroll
        for (int i = 0; i < 8; i++)
#pragma unroll
            for (int jj = 0; jj < 4; jj++) {
                float2 v = unpack2(acc[i][jj]);
                accf[i][2 * jj]     = v.x;
                accf[i][2 * jj + 1] = v.y;
            }

        // ---- epilogue: tanh + bilinear + mod -> vbuf[c][p] ----
#pragma unroll
        for (int j = 0; j < 8; j++) {
            int p = p0 + j;
            const float* mt = meta + p * 10;
            float glt = mt[0], grb = mt[1], glb = mt[2], grt = mt[3];
            int o00 = __float_as_int(mt[4]);
            int o11 = __float_as_int(mt[5]);
            int o01 = __float_as_int(mt[6]);
            int o10 = __float_as_int(mt[7]);
            float modk = mt[8];
#pragma unroll
            for (int i = 0; i < 8; i++) {
                const float* xc = xb + (mw8 + i) * HWn;
                float pos = glt * __ldg(xc + o00) + grb * __ldg(xc + o11)
                          + glb * __ldg(xc + o01) + grt * __ldg(xc + o10);
                float v = (tanhf(accf[i][j]) + pos) * modk;
                vbuf[(mw8 + i) * BB_STRIDE + p] = v;
            }
        }
        __syncthreads();

        // ---- GEMM2: oacc += WcT_k @ v (f32x2) ----
#pragma unroll 4
        for (int c = 0; c < 64; c++) {
            const double2* wd = (const double2*)(wbuf + c * WB2_STRIDE + mw * 20);
            const double2* bd = (const double2*)(vbuf + c * BB_STRIDE + p0);
            double2 a01 = wd[0], a23 = wd[1], a45 = wd[2], a67 = wd[3];
            double2 bq0 = bd[0], bq1 = bd[1];
            u64 ap[8] = {d2u_lo(a01), d2u_hi(a01), d2u_lo(a23), d2u_hi(a23),
                         d2u_lo(a45), d2u_hi(a45), d2u_lo(a67), d2u_hi(a67)};
            u64 bp[4] = {d2u_lo(bq0), d2u_hi(bq0), d2u_lo(bq1), d2u_hi(bq1)};
#pragma unroll
            for (int i = 0; i < 8; i++)
#pragma unroll
                for (int jj = 0; jj < 4; jj++)
                    ffma2(oacc[i][jj], ap[i], bp[jj]);
        }
    }

    // ---- store output ----
    int oh = h0 + (p0 >> 5), ow = w0 + (p0 & 31);
    float* ob = out + (size_t)b * 64 * HWn + oh * Wn + ow;
#pragma unroll
    for (int i = 0; i < 8; i++) {
        float2 v0 = unpack2(oacc[i][0]);
        float2 v1 = unpack2(oacc[i][1]);
        float2 v2 = unpack2(oacc[i][2]);
        float2 v3 = unpack2(oacc[i][3]);
        float* dst = ob + (mw8 + i) * HWn;
        *(float4*)(dst)     = make_float4(v0.x, v0.y, v1.x, v1.y);
        *(float4*)(dst + 4) = make_float4(v2.x, v2.y, v3.x, v3.y);
    }
}

// ============================================================
// launch
// ============================================================
extern "C" void kernel_launch(void* const* d_in, const int* in_sizes, int n_in,
                              void* d_out, int out_size)
{
    const float* x      = (const float*)d_in[0];
    const float* ref    = (const float*)d_in[1];
    const float* w_cd   = (const float*)d_in[2];
    const float* b_cd   = (const float*)d_in[3];
    const float* w_p    = (const float*)d_in[4];
    const float* b_p    = (const float*)d_in[5];
    const float* w_m    = (const float*)d_in[6];
    const float* b_m    = (const float*)d_in[7];
    const float* w_c    = (const float*)d_in[8];
    const float* b_c    = (const float*)d_in[9];
    const float* w_conv = (const float*)d_in[10];
    float* out = (float*)d_out;

    (void)in_sizes; (void)n_in; (void)out_size;

    size_t smem2 = (size_t)(HALO_SZ + 576 * 28) * sizeof(float);   // 151,552
    size_t smem3 = (size_t)SMEM_MAIN * sizeof(float);              // 219,392
    cudaFuncSetAttribute(k_offmod, cudaFuncAttributeMaxDynamicSharedMemorySize, (int)smem2);
    cudaFuncSetAttribute(k_main,   cudaFuncAttributeMaxDynamicSharedMemorySize, (int)smem3);

    k_wct<<<(K2n * 64 * 64 + 255) / 256, 256>>>(w_conv);
    k_fused<<<(Bn * HWn) / 256, 256>>>(x, ref, w_cd, b_cd);

    dim3 grid(Wn / TW, Hn / TH, Bn);   // (4, 16, 4)
    k_offmod<<<grid, 256, smem2>>>(w_p, b_p, w_m, b_m);
    k_main<<<grid, 256, smem3>>>(x, w_c, b_c, out);
}

// round 13
// speedup vs baseline: 1.8287x; 1.8287x over previous
#include <cuda_runtime.h>
#include <cuda_bf16.h>
#include <math.h>
#include <stdint.h>

typedef uint32_t u32;

// Problem constants
#define Bn   4
#define Cn   64
#define Hn   128
#define Wn   128
#define HWn  16384
#define TH   8
#define TW   32
#define HALO_H 10
#define HALO_W 34
#define HCH  (HALO_H * HALO_W)          // 340
#define HALO_SZ (Cn * HCH)              // 21760 words

// k_main dynamic smem byte offsets
#define OFF_FSP  0                      // 21760 u32 = 87040
#define OFF_BH   87040                  // 32 x 264 u32 = 33792 (im2col hi / vbuf hi)
#define OFF_BL   120832                 // 33792 (lo)
#define OFF_AH   154624                 // 64 x 36 u32 = 9216 (A stage hi)
#define OFF_AL   163840                 // 9216 (lo)
#define OFF_META 173056                 // 256 x 9 floats = 9216
#define SMEM_MAIN_BYTES 182272

#define BSTR 264                        // B row stride (u32)
#define ASTR 36                         // A row stride (u32)

// -------- device scratch (static; no runtime allocation) --------
__device__ float g_fused[Bn * Cn * HWn];
__device__ u32   g_fusedp[Bn * Cn * HWn];          // packed bf16 hi|lo<<16
__device__ float g_off[Bn * 2 * 9 * HWn];
__device__ float g_mod[Bn * 9 * HWn];
__device__ u32   g_w1hi[9 * 64 * 288];             // [(k*64+c)*288 + jp] bf16 pair (j even|odd)
__device__ u32   g_w1lo[9 * 64 * 288];
__device__ u32   g_w2hi[9 * 64 * 32];              // [(k*64+oc)*32 + c2] pair (c even|odd)
__device__ u32   g_w2lo[9 * 64 * 32];

// -------- helpers --------
__device__ __forceinline__ u32 pack_bf16_split(float v) {
    __nv_bfloat16 h = __float2bfloat16(v);
    __nv_bfloat16 l = __float2bfloat16(v - __bfloat162float(h));
    return (u32)__bfloat16_as_ushort(h) | ((u32)__bfloat16_as_ushort(l) << 16);
}

__device__ __forceinline__ void mma_bf16(float* c,
                                         u32 a0, u32 a1, u32 a2, u32 a3,
                                         u32 b0, u32 b1) {
    asm volatile(
        "mma.sync.aligned.m16n8k16.row.col.f32.bf16.bf16.f32 "
        "{%0,%1,%2,%3}, {%4,%5,%6,%7}, {%8,%9}, {%0,%1,%2,%3};"
        : "+f"(c[0]), "+f"(c[1]), "+f"(c[2]), "+f"(c[3])
        : "r"(a0), "r"(a1), "r"(a2), "r"(a3), "r"(b0), "r"(b1));
}

__device__ __forceinline__ float fast_tanh(float x) {
    float e = __expf(2.f * x);          // MUFU.EX2-based
    return 1.f - __fdividef(2.f, e + 1.f);   // rcp.approx; saturates correctly at +-inf
}

// ============================================================
// Prep: split wc into bf16 hi/lo pairs, rows m=c for tap k
// ============================================================
__global__ void k_prepW1(const float* __restrict__ wc) {
    int i = blockIdx.x * 256 + threadIdx.x;
    if (i >= 9 * 64 * 288) return;
    int jp = i % 288;
    int kc = i / 288;
    int c = kc & 63, k = kc >> 6;
    const float* row = wc + (size_t)(c * 9 + k) * 576;
    u32 p0 = pack_bf16_split(row[2 * jp]);
    u32 p1 = pack_bf16_split(row[2 * jp + 1]);
    g_w1hi[i] = __byte_perm(p0, p1, 0x5410);
    g_w1lo[i] = __byte_perm(p0, p1, 0x7632);
}

__global__ void k_prepW2(const float* __restrict__ wconv) {
    int i = blockIdx.x * 256 + threadIdx.x;
    if (i >= 9 * 64 * 32) return;
    int c2 = i & 31;
    int kc = i >> 5;
    int oc = kc & 63, k = kc >> 6;
    u32 p0 = pack_bf16_split(wconv[(size_t)oc * 576 + (2 * c2) * 9 + k]);
    u32 p1 = pack_bf16_split(wconv[(size_t)oc * 576 + (2 * c2 + 1) * 9 + k]);
    g_w2hi[i] = __byte_perm(p0, p1, 0x5410);
    g_w2lo[i] = __byte_perm(p0, p1, 0x7632);
}

// ============================================================
// Kernel 1: fused = 1x1 conv (128->64); fp32 + packed bf16 out
// ============================================================
__global__ void __launch_bounds__(256) k_fused(
    const float* __restrict__ x, const float* __restrict__ ref,
    const float* __restrict__ wcd, const float* __restrict__ bcd)
{
    __shared__ float ws[128 * 65];
    int tid = threadIdx.x;
    for (int i = tid; i < 128 * 64; i += 256) {
        int co = i >> 7, ci = i & 127;
        ws[ci * 65 + co] = wcd[i];
    }
    __syncthreads();

    int pid = blockIdx.x * 256 + tid;
    int b = pid >> 14;
    int p = pid & (HWn - 1);

    float acc[64];
#pragma unroll
    for (int co = 0; co < 64; co++) acc[co] = bcd[co];

    const float* xb = x   + (size_t)b * Cn * HWn + p;
    const float* rb = ref + (size_t)b * Cn * HWn + p;

    for (int ci = 0; ci < 64; ci++) {
        float v = __ldg(xb + ci * HWn);
        const float* w = ws + ci * 65;
#pragma unroll
        for (int co = 0; co < 64; co++) acc[co] += v * w[co];
    }
    for (int ci = 0; ci < 64; ci++) {
        float v = __ldg(rb + ci * HWn);
        const float* w = ws + (64 + ci) * 65;
#pragma unroll
        for (int co = 0; co < 64; co++) acc[co] += v * w[co];
    }

    float* o  = g_fused  + (size_t)b * Cn * HWn + p;
    u32*   op = g_fusedp + (size_t)b * Cn * HWn + p;
#pragma unroll
    for (int co = 0; co < 64; co++) {
        o[co * HWn]  = acc[co];
        op[co * HWn] = pack_bf16_split(acc[co]);
    }
}

// ============================================================
// Kernel 2: off (18ch) + mod (9ch, sigmoid), 3x3 conv pad 1
// ============================================================
__global__ void __launch_bounds__(256) k_offmod(
    const float* __restrict__ wp, const float* __restrict__ bp,
    const float* __restrict__ wm, const float* __restrict__ bm)
{
    extern __shared__ float sm[];
    float* fs  = sm;
    float* ws2 = sm + HALO_SZ;

    int tid = threadIdx.x;
    int b  = blockIdx.z;
    int h0 = blockIdx.y * TH;
    int w0 = blockIdx.x * TW;

    const float* fb = g_fused + (size_t)b * Cn * HWn;
    for (int i = tid; i < HALO_SZ; i += 256) {
        int ic = i / HCH;
        int rr = (i / HALO_W) % HALO_H;
        int cc = i % HALO_W;
        int gh = h0 - 1 + rr, gw = w0 - 1 + cc;
        float v = 0.f;
        if (gh >= 0 && gh < Hn && gw >= 0 && gw < Wn)
            v = fb[ic * HWn + gh * Wn + gw];
        fs[i] = v;
    }
    for (int i = tid; i < 27 * 576; i += 256) {
        int o = i / 576, j = i - o * 576;
        float v = (o < 18) ? wp[o * 576 + j] : wm[(o - 18) * 576 + j];
        ws2[j * 28 + o] = v;
    }
    __syncthreads();

    int ly = tid >> 5, lx = tid & 31;
    int base = ly * HALO_W + lx;

    float acc[27];
#pragma unroll
    for (int o = 0; o < 27; o++) acc[o] = (o < 18) ? bp[o] : bm[o - 18];

    for (int ic = 0; ic < 64; ic++) {
        float u[9];
#pragma unroll
        for (int t = 0; t < 9; t++)
            u[t] = fs[ic * HCH + base + (t / 3) * HALO_W + (t % 3)];
#pragma unroll
        for (int t = 0; t < 9; t++) {
            const float* w = ws2 + (ic * 9 + t) * 28;
#pragma unroll
            for (int o = 0; o < 27; o++) acc[o] += u[t] * w[o];
        }
    }

    int h = h0 + ly, w = w0 + lx;
    int pix = h * Wn + w;
#pragma unroll
    for (int o = 0; o < 18; o++)
        g_off[((size_t)b * 18 + o) * HWn + pix] = acc[o];
#pragma unroll
    for (int o = 0; o < 9; o++)
        g_mod[((size_t)b * 9 + o) * HWn + pix] = 1.f / (1.f + expf(-acc[18 + o]));
}

// ============================================================
// Kernel 3: main — warp-level bf16 HMMA (3-split) GEMMs + fused epilogue
// Warp tile: 32 m-rows x 64 pixels (2 m16 x 8 n8). 8 warps cover 64x256.
// ============================================================
__global__ void __launch_bounds__(256, 1) k_main(
    const float* __restrict__ x, const float* __restrict__ bc,
    float* __restrict__ out)
{
    extern __shared__ unsigned char smc[];
    u32*   fsp  = (u32*)(smc + OFF_FSP);
    u32*   bhw  = (u32*)(smc + OFF_BH);
    u32*   blw  = (u32*)(smc + OFF_BL);
    u32*   ahw  = (u32*)(smc + OFF_AH);
    u32*   alw  = (u32*)(smc + OFF_AL);
    float* meta = (float*)(smc + OFF_META);

    int tid  = threadIdx.x;
    int warp = tid >> 5;
    int lane = tid & 31;
    int b  = blockIdx.z;
    int h0 = blockIdx.y * TH;
    int w0 = blockIdx.x * TW;

    int mp = warp & 1;          // m half: rows mp*32 .. +31
    int ph = warp >> 1;         // pixel quarter: ph*64 .. +63

    // --- halo load (packed bf16 fused) ---
    const u32* fb = g_fusedp + (size_t)b * Cn * HWn;
    for (int i = tid; i < HALO_SZ; i += 256) {
        int ic = i / HCH;
        int rr = (i / HALO_W) % HALO_H;
        int cc = i % HALO_W;
        int gh = h0 - 1 + rr, gw = w0 - 1 + cc;
        u32 v = 0;
        if (gh >= 0 && gh < Hn && gw >= 0 && gw < Wn)
            v = fb[ic * HWn + gh * Wn + gw];
        fsp[i] = v;
    }

    int ly = tid >> 5, lx = tid & 31;
    int hh = h0 + ly, ww = w0 + lx;
    int pix = hh * Wn + ww;
    const float* xb = x + (size_t)b * Cn * HWn;

    // this thread's 4 conv-channel rows (fixed across taps)
    int cr = mp * 32 + (lane >> 2);
    const float* xc00 = xb + (cr +  0) * HWn;
    const float* xc01 = xb + (cr +  8) * HWn;
    const float* xc10 = xb + (cr + 16) * HWn;
    const float* xc11 = xb + (cr + 24) * HWn;

    int bp_self = (tid >> 5) * HALO_W + (tid & 31);  // (unused placeholder)
    (void)bp_self;

    float oacc[2][8][4];
#pragma unroll
    for (int t = 0; t < 2; t++)
#pragma unroll
        for (int nt = 0; nt < 8; nt++)
#pragma unroll
            for (int e = 0; e < 4; e++) oacc[t][nt][e] = 0.f;

    for (int k = 0; k < 9; k++) {
        // ---- sampling metadata: thread tid -> pixel tid ----
        {
            float offx = g_off[((size_t)b * 18 + k) * HWn + pix];
            float offy = g_off[((size_t)b * 18 + 9 + k) * HWn + pix];
            float modk = g_mod[((size_t)b * 9 + k) * HWn + pix];

            float px = (float)(hh + 1) + offx + (float)(k / 3 - 1);
            float py = (float)(ww + 1) + offy + (float)(k % 3 - 1);
            float fx = floorf(px), fy = floorf(py);
            float qltx = fminf(fmaxf(fx,       0.f), 129.f);
            float qlty = fminf(fmaxf(fy,       0.f), 129.f);
            float qrbx = fminf(fmaxf(fx + 1.f, 0.f), 129.f);
            float qrby = fminf(fmaxf(fy + 1.f, 0.f), 129.f);
            float sx = fminf(fmaxf(px, 0.f), 129.f);
            float sy = fminf(fmaxf(py, 0.f), 129.f);
            float glt = (1.f + qltx - sx) * (1.f + qlty - sy);
            float grb = (1.f - qrbx + sx) * (1.f - qrby + sy);
            float glb = (1.f + qltx - sx) * (1.f - qrby + sy);
            float grt = (1.f - qrbx + sx) * (1.f + qlty - sy);

            int ix0 = (int)qltx, iy0 = (int)qlty;
            int ix1 = (int)qrbx, iy1 = (int)qrby;
            bool vx0 = (ix0 >= 1 && ix0 <= 128), vy0 = (iy0 >= 1 && iy0 <= 128);
            bool vx1 = (ix1 >= 1 && ix1 <= 128), vy1 = (iy1 >= 1 && iy1 <= 128);
            bool v00 = vx0 && vy0, v11 = vx1 && vy1;
            bool v01 = vx0 && vy1, v10 = vx1 && vy0;
            int o00 = v00 ? ((ix0 - 1) * Wn + (iy0 - 1)) : 0;
            int o11 = v11 ? ((ix1 - 1) * Wn + (iy1 - 1)) : 0;
            int o01 = v01 ? ((ix0 - 1) * Wn + (iy1 - 1)) : 0;
            int o10 = v10 ? ((ix1 - 1) * Wn + (iy0 - 1)) : 0;

            float* mt = meta + tid * 9;
            mt[0] = v00 ? glt : 0.f;
            mt[1] = v11 ? grb : 0.f;
            mt[2] = v01 ? glb : 0.f;
            mt[3] = v10 ? grt : 0.f;
            mt[4] = __uint_as_float((u32)o00 | ((u32)o11 << 16));
            mt[5] = __uint_as_float((u32)o01 | ((u32)o10 << 16));
            mt[6] = modk;
        }

        // ---- GEMM1: conv[64 x 256], K=576 in 9 chunks of 64 ----
        float acc[2][8][4];
#pragma unroll
        for (int t = 0; t < 2; t++)
#pragma unroll
            for (int nt = 0; nt < 8; nt++)
#pragma unroll
                for (int e = 0; e < 4; e++) acc[t][nt][e] = 0.f;

        for (int s = 0; s < 9; s++) {
            __syncthreads();   // prev users of bbuf/awh done (incl. prev tap GEMM2)

            // build im2col pairs: rows jp 0..31, col p = tid
            {
                int p = tid;
                int bp = (p >> 5) * HALO_W + (p & 31);
#pragma unroll 4
                for (int jp = 0; jp < 32; jp++) {
                    int j0 = s * 64 + 2 * jp;
                    int ic0 = j0 / 9, t0 = j0 - ic0 * 9;
                    int j1 = j0 + 1;
                    int ic1 = j1 / 9, t1 = j1 - ic1 * 9;
                    u32 w0v = fsp[ic0 * HCH + bp + (t0 / 3) * HALO_W + (t0 % 3)];
                    u32 w1v = fsp[ic1 * HCH + bp + (t1 / 3) * HALO_W + (t1 % 3)];
                    bhw[jp * BSTR + p] = __byte_perm(w0v, w1v, 0x5410);
                    blw[jp * BSTR + p] = __byte_perm(w0v, w1v, 0x7632);
                }
            }
            // stage A pairs: [64 m][32 q]
            {
                const u32* sh = g_w1hi + (size_t)(k * 64) * 288 + s * 32;
                const u32* sl = g_w1lo + (size_t)(k * 64) * 288 + s * 32;
                for (int i = tid; i < 2048; i += 256) {
                    int m = i >> 5, q = i & 31;
                    ahw[m * ASTR + q] = sh[m * 288 + q];
                    alw[m * ASTR + q] = sl[m * 288 + q];
                }
            }
            __syncthreads();

#pragma unroll
            for (int ks = 0; ks < 4; ks++) {
                int k2 = ks * 8 + (lane & 3);
                u32 Ah[2][4], Al[2][4];
#pragma unroll
                for (int t = 0; t < 2; t++) {
                    int rb = (mp * 32 + t * 16 + (lane >> 2)) * ASTR;
                    Ah[t][0] = ahw[rb + k2];
                    Ah[t][1] = ahw[rb + 8 * ASTR + k2];
                    Ah[t][2] = ahw[rb + k2 + 4];
                    Ah[t][3] = ahw[rb + 8 * ASTR + k2 + 4];
                    Al[t][0] = alw[rb + k2];
                    Al[t][1] = alw[rb + 8 * ASTR + k2];
                    Al[t][2] = alw[rb + k2 + 4];
                    Al[t][3] = alw[rb + 8 * ASTR + k2 + 4];
                }
                int nb = ph * 64 + (lane >> 2);
#pragma unroll
                for (int nt = 0; nt < 8; nt++) {
                    int n = nb + nt * 8;
                    u32 b0h = bhw[k2 * BSTR + n];
                    u32 b1h = bhw[(k2 + 4) * BSTR + n];
                    u32 b0l = blw[k2 * BSTR + n];
                    u32 b1l = blw[(k2 + 4) * BSTR + n];
#pragma unroll
                    for (int t = 0; t < 2; t++) {
                        mma_bf16(acc[t][nt], Ah[t][0], Ah[t][1], Ah[t][2], Ah[t][3], b0h, b1h);
                        mma_bf16(acc[t][nt], Ah[t][0], Ah[t][1], Ah[t][2], Ah[t][3], b0l, b1l);
                        mma_bf16(acc[t][nt], Al[t][0], Al[t][1], Al[t][2], Al[t][3], b0h, b1h);
                    }
                }
            }
        }

        __syncthreads();   // GEMM1 reads of bbuf/awh complete

        // ---- stage A2 (WcT pairs) into awh/alw ----
        {
            const u32* sh = g_w2hi + (size_t)(k * 64) * 32;
            const u32* sl = g_w2lo + (size_t)(k * 64) * 32;
            for (int i = tid; i < 2048; i += 256) {
                int m = i >> 5, q = i & 31;
                ahw[m * ASTR + q] = sh[m * 32 + q];
                alw[m * ASTR + q] = sl[m * 32 + q];
            }
        }

        // ---- epilogue: bias + tanh + bilinear + mod -> vbuf (reuses bbuf) ----
        {
            float bias[2][2];
            const float* xcs[2][2] = {{xc00, xc01}, {xc10, xc11}};
#pragma unroll
            for (int t = 0; t < 2; t++)
#pragma unroll
                for (int hf = 0; hf < 2; hf++)
                    bias[t][hf] = bc[(cr + t * 16 + hf * 8) * 9 + k];

#pragma unroll
            for (int t = 0; t < 2; t++) {
#pragma unroll
                for (int nt = 0; nt < 8; nt++) {
                    int pA = ph * 64 + nt * 8 + (lane & 3) * 2;
#pragma unroll
                    for (int hf = 0; hf < 2; hf++) {
                        int c  = cr + t * 16 + hf * 8;
                        int c2 = c >> 1;
                        u32 halfoff = (u32)(c & 1) << 1;
                        const float* xc = xcs[t][hf];
#pragma unroll
                        for (int e = 0; e < 2; e++) {
                            int p = pA + e;
                            const float* mt = meta + p * 9;
                            u32 pk0 = __float_as_uint(mt[4]);
                            u32 pk1 = __float_as_uint(mt[5]);
                            float pos = mt[0] * __ldg(xc + (pk0 & 0xFFFF))
                                      + mt[1] * __ldg(xc + (pk0 >> 16))
                                      + mt[2] * __ldg(xc + (pk1 & 0xFFFF))
                                      + mt[3] * __ldg(xc + (pk1 >> 16));
                            float conv = acc[t][nt][hf * 2 + e] + bias[t][hf];
                            float v = (fast_tanh(conv) + pos) * mt[6];
                            u32 pk = pack_bf16_split(v);
                            u32 woff = (u32)(c2 * BSTR + p) << 2;
                            *(unsigned short*)(smc + OFF_BH + woff + halfoff)
                                = (unsigned short)(pk & 0xFFFF);
                            *(unsigned short*)(smc + OFF_BL + woff + halfoff)
                                = (unsigned short)(pk >> 16);
                        }
                    }
                }
            }
        }
        __syncthreads();   // vbuf + A2 visible

        // ---- GEMM2: oacc += W2[64 x 64] @ v[64 x 256], 4 k-steps ----
#pragma unroll
        for (int ks = 0; ks < 4; ks++) {
            int k2 = ks * 8 + (lane & 3);
            u32 Ah[2][4], Al[2][4];
#pragma unroll
            for (int t = 0; t < 2; t++) {
                int rb = (mp * 32 + t * 16 + (lane >> 2)) * ASTR;
                Ah[t][0] = ahw[rb + k2];
                Ah[t][1] = ahw[rb + 8 * ASTR + k2];
                Ah[t][2] = ahw[rb + k2 + 4];
                Ah[t][3] = ahw[rb + 8 * ASTR + k2 + 4];
                Al[t][0] = alw[rb + k2];
                Al[t][1] = alw[rb + 8 * ASTR + k2];
                Al[t][2] = alw[rb + k2 + 4];
                Al[t][3] = alw[rb + 8 * ASTR + k2 + 4];
            }
            int nb = ph * 64 + (lane >> 2);
#pragma unroll
            for (int nt = 0; nt < 8; nt++) {
                int n = nb + nt * 8;
                u32 b0h = bhw[k2 * BSTR + n];
                u32 b1h = bhw[(k2 + 4) * BSTR + n];
                u32 b0l = blw[k2 * BSTR + n];
                u32 b1l = blw[(k2 + 4) * BSTR + n];
#pragma unroll
                for (int t = 0; t < 2; t++) {
                    mma_bf16(oacc[t][nt], Ah[t][0], Ah[t][1], Ah[t][2], Ah[t][3], b0h, b1h);
                    mma_bf16(oacc[t][nt], Ah[t][0], Ah[t][1], Ah[t][2], Ah[t][3], b0l, b1l);
                    mma_bf16(oacc[t][nt], Al[t][0], Al[t][1], Al[t][2], Al[t][3], b0h, b1h);
                }
            }
        }
    }

    // ---- store output: float2 per (row, col-pair) ----
#pragma unroll
    for (int t = 0; t < 2; t++) {
#pragma unroll
        for (int nt = 0; nt < 8; nt++) {
            int p = ph * 64 + nt * 8 + (lane & 3) * 2;
            int oh = h0 + (p >> 5), ow = w0 + (p & 31);
#pragma unroll
            for (int hf = 0; hf < 2; hf++) {
                int oc = cr + t * 16 + hf * 8;
                float2 v = make_float2(oacc[t][nt][hf * 2 + 0], oacc[t][nt][hf * 2 + 1]);
                *(float2*)(out + ((size_t)b * 64 + oc) * HWn + oh * Wn + ow) = v;
            }
        }
    }
}

// ============================================================
// launch
// ============================================================
extern "C" void kernel_launch(void* const* d_in, const int* in_sizes, int n_in,
                              void* d_out, int out_size)
{
    const float* x      = (const float*)d_in[0];
    const float* ref    = (const float*)d_in[1];
    const float* w_cd   = (const float*)d_in[2];
    const float* b_cd   = (const float*)d_in[3];
    const float* w_p    = (const float*)d_in[4];
    const float* b_p    = (const float*)d_in[5];
    const float* w_m    = (const float*)d_in[6];
    const float* b_m    = (const float*)d_in[7];
    const float* w_c    = (const float*)d_in[8];
    const float* b_c    = (const float*)d_in[9];
    const float* w_conv = (const float*)d_in[10];
    float* out = (float*)d_out;

    (void)in_sizes; (void)n_in; (void)out_size;

    size_t smem2 = (size_t)(HALO_SZ + 576 * 28) * sizeof(float);   // 151,552
    cudaFuncSetAttribute(k_offmod, cudaFuncAttributeMaxDynamicSharedMemorySize, (int)smem2);
    cudaFuncSetAttribute(k_main,   cudaFuncAttributeMaxDynamicSharedMemorySize, SMEM_MAIN_BYTES);

    k_prepW1<<<(9 * 64 * 288 + 255) / 256, 256>>>(w_c);
    k_prepW2<<<(9 * 64 * 32 + 255) / 256, 256>>>(w_conv);
    k_fused<<<(Bn * HWn) / 256, 256>>>(x, ref, w_cd, b_cd);

    dim3 grid(Wn / TW, Hn / TH, Bn);   // (4, 16, 4)
    k_offmod<<<grid, 256, smem2>>>(w_p, b_p, w_m, b_m);
    k_main<<<grid, 256, SMEM_MAIN_BYTES>>>(x, b_c, out);
}

// round 14
// speedup vs baseline: 2.0408x; 1.1160x over previous
#include <cuda_runtime.h>
#include <cuda_bf16.h>
#include <math.h>
#include <stdint.h>

typedef uint32_t u32;

// Problem constants
#define Bn   4
#define Cn   64
#define Hn   128
#define Wn   128
#define HWn  16384
#define TH   8
#define TW   32
#define HALO_H 10
#define HALO_W 34
#define HCH  (HALO_H * HALO_W)          // 340
#define HALO_SZ (Cn * HCH)              // 21760 words

// k_main dynamic smem byte offsets
#define OFF_FSP  0                      // 21760 u32 = 87040
#define OFF_BH   87040                  // 32 x 264 u32 = 33792 (im2col hi / vbuf hi)
#define OFF_BL   120832                 // 33792 (lo)
#define OFF_A    154624                 // 2 x (64 x 44 u32 hi + same lo) = 45056
#define OFF_META 199680                 // 256 x 9 floats = 9216
#define OFF_TBL  208896                 // 288 u32 = 1152
#define SMEM_MAIN_BYTES 210048

#define BSTR 264                        // B row stride (u32)
#define ASTR 44                         // A row stride (u32): 16B-aligned + conflict-free
#define A_SEL_BYTES 22528               // one A buffer (hi 11264 + lo 11264)
#define A_LO_U32 2816                   // lo offset within buffer, in u32

// -------- device scratch (static; no runtime allocation) --------
__device__ float g_fused[Bn * Cn * HWn];
__device__ u32   g_fusedp[Bn * Cn * HWn];          // packed bf16 hi|lo<<16
__device__ float g_off[Bn * 2 * 9 * HWn];
__device__ float g_mod[Bn * 9 * HWn];
__device__ u32   g_w1hi[9 * 64 * 288];             // [(k*64+c)*288 + jp] bf16 pair (j even|odd)
__device__ u32   g_w1lo[9 * 64 * 288];
__device__ u32   g_w2hi[9 * 64 * 32];              // [(k*64+oc)*32 + c2] pair (c even|odd)
__device__ u32   g_w2lo[9 * 64 * 32];

// -------- helpers --------
__device__ __forceinline__ u32 pack_bf16_split(float v) {
    __nv_bfloat16 h = __float2bfloat16(v);
    __nv_bfloat16 l = __float2bfloat16(v - __bfloat162float(h));
    return (u32)__bfloat16_as_ushort(h) | ((u32)__bfloat16_as_ushort(l) << 16);
}

__device__ __forceinline__ void mma_bf16(float* c,
                                         u32 a0, u32 a1, u32 a2, u32 a3,
                                         u32 b0, u32 b1) {
    asm volatile(
        "mma.sync.aligned.m16n8k16.row.col.f32.bf16.bf16.f32 "
        "{%0,%1,%2,%3}, {%4,%5,%6,%7}, {%8,%9}, {%0,%1,%2,%3};"
        : "+f"(c[0]), "+f"(c[1]), "+f"(c[2]), "+f"(c[3])
        : "r"(a0), "r"(a1), "r"(a2), "r"(a3), "r"(b0), "r"(b1));
}

__device__ __forceinline__ float fast_tanh(float x) {
    float e = __expf(2.f * x);
    return 1.f - __fdividef(2.f, e + 1.f);
}

__device__ __forceinline__ u32 smem_u32(const void* p) {
    u32 a;
    asm("{ .reg .u64 t; cvta.to.shared.u64 t, %1; cvt.u32.u64 %0, t; }"
        : "=r"(a) : "l"(p));
    return a;
}

__device__ __forceinline__ void cp16(u32 dst_smem, const void* src) {
    asm volatile("cp.async.cg.shared.global [%0], [%1], 16;"
                 :: "r"(dst_smem), "l"(src) : "memory");
}
#define CP_COMMIT() asm volatile("cp.async.commit_group;" ::: "memory")
#define CP_WAIT1()  asm volatile("cp.async.wait_group 1;" ::: "memory")
#define CP_WAIT0()  asm volatile("cp.async.wait_group 0;" ::: "memory")

// async-stage one 64x32(u32) A block (hi+lo) into A buffer `sel`
__device__ __forceinline__ void cp_A(u32 abase_smem, int sel,
                                     const u32* srch, const u32* srcl,
                                     int src_stride, int tid) {
    u32 dh = abase_smem + (u32)sel * A_SEL_BYTES;
    u32 dl = dh + A_LO_U32 * 4;
#pragma unroll
    for (int part = 0; part < 2; part++) {
        int idx = part * 256 + tid;
        int row = idx >> 3, seg = idx & 7;
        u32 doff = (u32)(row * ASTR + seg * 4) * 4;
        cp16(dh + doff, srch + row * src_stride + seg * 4);
        cp16(dl + doff, srcl + row * src_stride + seg * 4);
    }
}

// ============================================================
// Prep (merged): split weights into bf16 hi/lo pairs
// ============================================================
__global__ void k_prep(const float* __restrict__ wc, const float* __restrict__ wconv) {
    int i = blockIdx.x * 256 + threadIdx.x;
    if (i < 9 * 64 * 288) {
        int jp = i % 288;
        int kc = i / 288;
        int c = kc & 63, k = kc >> 6;
        const float* row = wc + (size_t)(c * 9 + k) * 576;
        u32 p0 = pack_bf16_split(row[2 * jp]);
        u32 p1 = pack_bf16_split(row[2 * jp + 1]);
        g_w1hi[i] = __byte_perm(p0, p1, 0x5410);
        g_w1lo[i] = __byte_perm(p0, p1, 0x7632);
    }
    int j = i - 9 * 64 * 288;
    if (j >= 0 && j < 9 * 64 * 32) {
        int c2 = j & 31;
        int kc = j >> 5;
        int oc = kc & 63, k = kc >> 6;
        u32 p0 = pack_bf16_split(wconv[(size_t)oc * 576 + (2 * c2) * 9 + k]);
        u32 p1 = pack_bf16_split(wconv[(size_t)oc * 576 + (2 * c2 + 1) * 9 + k]);
        g_w2hi[j] = __byte_perm(p0, p1, 0x5410);
        g_w2lo[j] = __byte_perm(p0, p1, 0x7632);
    }
}

// ============================================================
// Kernel 1: fused = 1x1 conv (128->64); fp32 + packed bf16 out
// ============================================================
__global__ void __launch_bounds__(256) k_fused(
    const float* __restrict__ x, const float* __restrict__ ref,
    const float* __restrict__ wcd, const float* __restrict__ bcd)
{
    __shared__ float ws[128 * 65];
    int tid = threadIdx.x;
    for (int i = tid; i < 128 * 64; i += 256) {
        int co = i >> 7, ci = i & 127;
        ws[ci * 65 + co] = wcd[i];
    }
    __syncthreads();

    int pid = blockIdx.x * 256 + tid;
    int b = pid >> 14;
    int p = pid & (HWn - 1);

    float acc[64];
#pragma unroll
    for (int co = 0; co < 64; co++) acc[co] = bcd[co];

    const float* xb = x   + (size_t)b * Cn * HWn + p;
    const float* rb = ref + (size_t)b * Cn * HWn + p;

    for (int ci = 0; ci < 64; ci++) {
        float v = __ldg(xb + ci * HWn);
        const float* w = ws + ci * 65;
#pragma unroll
        for (int co = 0; co < 64; co++) acc[co] += v * w[co];
    }
    for (int ci = 0; ci < 64; ci++) {
        float v = __ldg(rb + ci * HWn);
        const float* w = ws + (64 + ci) * 65;
#pragma unroll
        for (int co = 0; co < 64; co++) acc[co] += v * w[co];
    }

    float* o  = g_fused  + (size_t)b * Cn * HWn + p;
    u32*   op = g_fusedp + (size_t)b * Cn * HWn + p;
#pragma unroll
    for (int co = 0; co < 64; co++) {
        o[co * HWn]  = acc[co];
        op[co * HWn] = pack_bf16_split(acc[co]);
    }
}

// ============================================================
// Kernel 2: off (18ch) + mod (9ch, sigmoid), 3x3 conv pad 1.
// No halo smem: reads g_fused via L2 directly -> 3 CTAs/SM.
// ============================================================
__global__ void __launch_bounds__(256) k_offmod(
    const float* __restrict__ wp, const float* __restrict__ bp,
    const float* __restrict__ wm, const float* __restrict__ bm)
{
    extern __shared__ float ws2[];   // [576][28]

    int tid = threadIdx.x;
    int b  = blockIdx.z;
    int h0 = blockIdx.y * TH;
    int w0 = blockIdx.x * TW;

    for (int i = tid; i < 27 * 576; i += 256) {
        int o = i / 576, j = i - o * 576;
        float v = (o < 18) ? wp[o * 576 + j] : wm[(o - 18) * 576 + j];
        ws2[j * 28 + o] = v;
    }
    __syncthreads();

    int ly = tid >> 5, lx = tid & 31;
    int h = h0 + ly, w = w0 + lx;

    // per-tap gather offsets + validity (zero pad)
    int  offp[9];
    bool valm[9];
#pragma unroll
    for (int t = 0; t < 9; t++) {
        int gh = h - 1 + t / 3, gw = w - 1 + t % 3;
        bool v = (gh >= 0 && gh < Hn && gw >= 0 && gw < Wn);
        valm[t] = v;
        offp[t] = v ? (gh * Wn + gw) : 0;
    }

    const float* fb = g_fused + (size_t)b * Cn * HWn;

    float acc[27];
#pragma unroll
    for (int o = 0; o < 27; o++) acc[o] = (o < 18) ? bp[o] : bm[o - 18];

    for (int ic = 0; ic < 64; ic++) {
        const float* base = fb + ic * HWn;
        float u[9];
#pragma unroll
        for (int t = 0; t < 9; t++)
            u[t] = valm[t] ? __ldg(base + offp[t]) : 0.f;
#pragma unroll
        for (int t = 0; t < 9; t++) {
            const float* wv = ws2 + (ic * 9 + t) * 28;
#pragma unroll
            for (int o = 0; o < 27; o++) acc[o] += u[t] * wv[o];
        }
    }

    int pix = h * Wn + w;
#pragma unroll
    for (int o = 0; o < 18; o++)
        g_off[((size_t)b * 18 + o) * HWn + pix] = acc[o];
#pragma unroll
    for (int o = 0; o < 9; o++)
        g_mod[((size_t)b * 9 + o) * HWn + pix] = 1.f / (1.f + expf(-acc[18 + o]));
}

// ============================================================
// Kernel 3: main — warp-level bf16 HMMA (3-split) GEMMs,
// cp.async double-buffered A, table-driven im2col.
// Warp tile: 32 m-rows x 64 pixels. 8 warps cover 64x256.
// ============================================================
__global__ void __launch_bounds__(256, 1) k_main(
    const float* __restrict__ x, const float* __restrict__ bc,
    float* __restrict__ out)
{
    extern __shared__ unsigned char smc[];
    u32*   fsp  = (u32*)(smc + OFF_FSP);
    u32*   bhw  = (u32*)(smc + OFF_BH);
    u32*   blw  = (u32*)(smc + OFF_BL);
    float* meta = (float*)(smc + OFF_META);
    u32*   tbl  = (u32*)(smc + OFF_TBL);

    u32 abase = smem_u32(smc) + OFF_A;

    int tid  = threadIdx.x;
    int warp = tid >> 5;
    int lane = tid & 31;
    int b  = blockIdx.z;
    int h0 = blockIdx.y * TH;
    int w0 = blockIdx.x * TW;

    int mp = warp & 1;          // m half: rows mp*32 .. +31
    int ph = warp >> 1;         // pixel quarter: ph*64 .. +63

    // --- halo load (packed bf16 fused) ---
    const u32* fb = g_fusedp + (size_t)b * Cn * HWn;
    for (int i = tid; i < HALO_SZ; i += 256) {
        int ic = i / HCH;
        int rr = (i / HALO_W) % HALO_H;
        int cc = i % HALO_W;
        int gh = h0 - 1 + rr, gw = w0 - 1 + cc;
        u32 v = 0;
        if (gh >= 0 && gh < Hn && gw >= 0 && gw < Wn)
            v = fb[ic * HWn + gh * Wn + gw];
        fsp[i] = v;
    }
    // --- im2col offset table: pair (j, j+1) packed as two u16 ---
    for (int i = tid; i < 288; i += 256) {
        int j0 = 2 * i, j1 = 2 * i + 1;
        int ic0 = j0 / 9, t0 = j0 - ic0 * 9;
        int ic1 = j1 / 9, t1 = j1 - ic1 * 9;
        u32 o0 = (u32)(ic0 * HCH + (t0 / 3) * HALO_W + (t0 % 3));
        u32 o1 = (u32)(ic1 * HCH + (t1 / 3) * HALO_W + (t1 % 3));
        tbl[i] = o0 | (o1 << 16);
    }

    int ly = tid >> 5, lx = tid & 31;
    int hh = h0 + ly, ww = w0 + lx;
    int pix = hh * Wn + ww;
    int bp = ly * HALO_W + lx;
    const float* xb = x + (size_t)b * Cn * HWn;

    int cr = mp * 32 + (lane >> 2);
    const float* xc00 = xb + (cr +  0) * HWn;
    const float* xc01 = xb + (cr +  8) * HWn;
    const float* xc10 = xb + (cr + 16) * HWn;
    const float* xc11 = xb + (cr + 24) * HWn;

    float oacc[2][8][4];
#pragma unroll
    for (int t = 0; t < 2; t++)
#pragma unroll
        for (int nt = 0; nt < 8; nt++)
#pragma unroll
            for (int e = 0; e < 4; e++) oacc[t][nt][e] = 0.f;

    // prologue: prefetch A1(k=0, s=0) into buffer 0
    int sel = 0;
    cp_A(abase, 0, g_w1hi, g_w1lo, 288, tid);
    CP_COMMIT();

    for (int k = 0; k < 9; k++) {
        // ---- sampling metadata: thread tid -> pixel tid ----
        {
            float offx = g_off[((size_t)b * 18 + k) * HWn + pix];
            float offy = g_off[((size_t)b * 18 + 9 + k) * HWn + pix];
            float modk = g_mod[((size_t)b * 9 + k) * HWn + pix];

            float px = (float)(hh + 1) + offx + (float)(k / 3 - 1);
            float py = (float)(ww + 1) + offy + (float)(k % 3 - 1);
            float fx = floorf(px), fy = floorf(py);
            float qltx = fminf(fmaxf(fx,       0.f), 129.f);
            float qlty = fminf(fmaxf(fy,       0.f), 129.f);
            float qrbx = fminf(fmaxf(fx + 1.f, 0.f), 129.f);
            float qrby = fminf(fmaxf(fy + 1.f, 0.f), 129.f);
            float sx = fminf(fmaxf(px, 0.f), 129.f);
            float sy = fminf(fmaxf(py, 0.f), 129.f);
            float glt = (1.f + qltx - sx) * (1.f + qlty - sy);
            float grb = (1.f - qrbx + sx) * (1.f - qrby + sy);
            float glb = (1.f + qltx - sx) * (1.f - qrby + sy);
            float grt = (1.f - qrbx + sx) * (1.f + qlty - sy);

            int ix0 = (int)qltx, iy0 = (int)qlty;
            int ix1 = (int)qrbx, iy1 = (int)qrby;
            bool vx0 = (ix0 >= 1 && ix0 <= 128), vy0 = (iy0 >= 1 && iy0 <= 128);
            bool vx1 = (ix1 >= 1 && ix1 <= 128), vy1 = (iy1 >= 1 && iy1 <= 128);
            bool v00 = vx0 && vy0, v11 = vx1 && vy1;
            bool v01 = vx0 && vy1, v10 = vx1 && vy0;
            int o00 = v00 ? ((ix0 - 1) * Wn + (iy0 - 1)) : 0;
            int o11 = v11 ? ((ix1 - 1) * Wn + (iy1 - 1)) : 0;
            int o01 = v01 ? ((ix0 - 1) * Wn + (iy1 - 1)) : 0;
            int o10 = v10 ? ((ix1 - 1) * Wn + (iy0 - 1)) : 0;

            float* mt = meta + tid * 9;
            mt[0] = v00 ? glt : 0.f;
            mt[1] = v11 ? grb : 0.f;
            mt[2] = v01 ? glb : 0.f;
            mt[3] = v10 ? grt : 0.f;
            mt[4] = __uint_as_float((u32)o00 | ((u32)o11 << 16));
            mt[5] = __uint_as_float((u32)o01 | ((u32)o10 << 16));
            mt[6] = modk;
        }

        // ---- GEMM1: conv[64 x 256], K=576 in 9 chunks of 64 ----
        float acc[2][8][4];
#pragma unroll
        for (int t = 0; t < 2; t++)
#pragma unroll
            for (int nt = 0; nt < 8; nt++)
#pragma unroll
                for (int e = 0; e < 4; e++) acc[t][nt][e] = 0.f;

        for (int s = 0; s < 9; s++) {
            __syncthreads();   // prev users of B done

            // build im2col pairs via offset table
            {
                const u32* ts = tbl + s * 32;
#pragma unroll
                for (int jp = 0; jp < 32; jp++) {
                    u32 oo = ts[jp];
                    u32 w0v = fsp[(oo & 0xFFFF) + bp];
                    u32 w1v = fsp[(oo >> 16) + bp];
                    bhw[jp * BSTR + tid] = __byte_perm(w0v, w1v, 0x5410);
                    blw[jp * BSTR + tid] = __byte_perm(w0v, w1v, 0x7632);
                }
            }
            // prefetch next A block (next chunk, or this tap's W2)
            if (s < 8)
                cp_A(abase, sel ^ 1,
                     g_w1hi + (size_t)(k * 64) * 288 + (s + 1) * 32,
                     g_w1lo + (size_t)(k * 64) * 288 + (s + 1) * 32, 288, tid);
            else
                cp_A(abase, sel ^ 1,
                     g_w2hi + (size_t)(k * 64) * 32,
                     g_w2lo + (size_t)(k * 64) * 32, 32, tid);
            CP_COMMIT();
            CP_WAIT1();        // current buffer ready
            __syncthreads();

            const u32* ahw = (const u32*)(smc + OFF_A + sel * A_SEL_BYTES);
            const u32* alw = ahw + A_LO_U32;

#pragma unroll
            for (int ks = 0; ks < 4; ks++) {
                int k2 = ks * 8 + (lane & 3);
                u32 Ah[2][4], Al[2][4];
#pragma unroll
                for (int t = 0; t < 2; t++) {
                    int rb = (mp * 32 + t * 16 + (lane >> 2)) * ASTR;
                    Ah[t][0] = ahw[rb + k2];
                    Ah[t][1] = ahw[rb + 8 * ASTR + k2];
                    Ah[t][2] = ahw[rb + k2 + 4];
                    Ah[t][3] = ahw[rb + 8 * ASTR + k2 + 4];
                    Al[t][0] = alw[rb + k2];
                    Al[t][1] = alw[rb + 8 * ASTR + k2];
                    Al[t][2] = alw[rb + k2 + 4];
                    Al[t][3] = alw[rb + 8 * ASTR + k2 + 4];
                }
                int nb = ph * 64 + (lane >> 2);
#pragma unroll
                for (int nt = 0; nt < 8; nt++) {
                    int n = nb + nt * 8;
                    u32 b0h = bhw[k2 * BSTR + n];
                    u32 b1h = bhw[(k2 + 4) * BSTR + n];
                    u32 b0l = blw[k2 * BSTR + n];
                    u32 b1l = blw[(k2 + 4) * BSTR + n];
#pragma unroll
                    for (int t = 0; t < 2; t++) {
                        mma_bf16(acc[t][nt], Ah[t][0], Ah[t][1], Ah[t][2], Ah[t][3], b0h, b1h);
                        mma_bf16(acc[t][nt], Ah[t][0], Ah[t][1], Ah[t][2], Ah[t][3], b0l, b1l);
                        mma_bf16(acc[t][nt], Al[t][0], Al[t][1], Al[t][2], Al[t][3], b0h, b1h);
                    }
                }
            }
            sel ^= 1;
        }

        __syncthreads();   // GEMM1 reads of B complete

        // prefetch next tap's first A1 chunk; ensure this tap's W2 landed
        if (k < 8) {
            cp_A(abase, sel ^ 1,
                 g_w1hi + (size_t)((k + 1) * 64) * 288,
                 g_w1lo + (size_t)((k + 1) * 64) * 288, 288, tid);
            CP_COMMIT();
            CP_WAIT1();
        } else {
            CP_WAIT0();
        }

        // ---- epilogue: bias + tanh + bilinear + mod -> vbuf (reuses B) ----
        {
            float bias[2][2];
            const float* xcs[2][2] = {{xc00, xc01}, {xc10, xc11}};
#pragma unroll
            for (int t = 0; t < 2; t++)
#pragma unroll
                for (int hf = 0; hf < 2; hf++)
                    bias[t][hf] = bc[(cr + t * 16 + hf * 8) * 9 + k];

#pragma unroll
            for (int t = 0; t < 2; t++) {
#pragma unroll
                for (int nt = 0; nt < 8; nt++) {
                    int pA = ph * 64 + nt * 8 + (lane & 3) * 2;
#pragma unroll
                    for (int hf = 0; hf < 2; hf++) {
                        int c  = cr + t * 16 + hf * 8;
                        int c2 = c >> 1;
                        u32 halfoff = (u32)(c & 1) << 1;
                        const float* xc = xcs[t][hf];
#pragma unroll
                        for (int e = 0; e < 2; e++) {
                            int p = pA + e;
                            const float* mt = meta + p * 9;
                            u32 pk0 = __float_as_uint(mt[4]);
                            u32 pk1 = __float_as_uint(mt[5]);
                            float pos = mt[0] * __ldg(xc + (pk0 & 0xFFFF))
                                      + mt[1] * __ldg(xc + (pk0 >> 16))
                                      + mt[2] * __ldg(xc + (pk1 & 0xFFFF))
                                      + mt[3] * __ldg(xc + (pk1 >> 16));
                            float conv = acc[t][nt][hf * 2 + e] + bias[t][hf];
                            float v = (fast_tanh(conv) + pos) * mt[6];
                            u32 pk = pack_bf16_split(v);
                            u32 woff = (u32)(c2 * BSTR + p) << 2;
                            *(unsigned short*)(smc + OFF_BH + woff + halfoff)
                                = (unsigned short)(pk & 0xFFFF);
                            *(unsigned short*)(smc + OFF_BL + woff + halfoff)
                                = (unsigned short)(pk >> 16);
                        }
                    }
                }
            }
        }
        __syncthreads();   // vbuf visible (W2 already waited)

        // ---- GEMM2: oacc += W2[64 x 64] @ v[64 x 256] ----
        {
            const u32* ahw = (const u32*)(smc + OFF_A + sel * A_SEL_BYTES);
            const u32* alw = ahw + A_LO_U32;
#pragma unroll
            for (int ks = 0; ks < 4; ks++) {
                int k2 = ks * 8 + (lane & 3);
                u32 Ah[2][4], Al[2][4];
#pragma unroll
                for (int t = 0; t < 2; t++) {
                    int rb = (mp * 32 + t * 16 + (lane >> 2)) * ASTR;
                    Ah[t][0] = ahw[rb + k2];
                    Ah[t][1] = ahw[rb + 8 * ASTR + k2];
                    Ah[t][2] = ahw[rb + k2 + 4];
                    Ah[t][3] = ahw[rb + 8 * ASTR + k2 + 4];
                    Al[t][0] = alw[rb + k2];
                    Al[t][1] = alw[rb + 8 * ASTR + k2];
                    Al[t][2] = alw[rb + k2 + 4];
                    Al[t][3] = alw[rb + 8 * ASTR + k2 + 4];
                }
                int nb = ph * 64 + (lane >> 2);
#pragma unroll
                for (int nt = 0; nt < 8; nt++) {
                    int n = nb + nt * 8;
                    u32 b0h = bhw[k2 * BSTR + n];
                    u32 b1h = bhw[(k2 + 4) * BSTR + n];
                    u32 b0l = blw[k2 * BSTR + n];
                    u32 b1l = blw[(k2 + 4) * BSTR + n];
#pragma unroll
                    for (int t = 0; t < 2; t++) {
                        mma_bf16(oacc[t][nt], Ah[t][0], Ah[t][1], Ah[t][2], Ah[t][3], b0h, b1h);
                        mma_bf16(oacc[t][nt], Ah[t][0], Ah[t][1], Ah[t][2], Ah[t][3], b0l, b1l);
                        mma_bf16(oacc[t][nt], Al[t][0], Al[t][1], Al[t][2], Al[t][3], b0h, b1h);
                    }
                }
            }
        }
        sel ^= 1;
    }

    // ---- store output ----
#pragma unroll
    for (int t = 0; t < 2; t++) {
#pragma unroll
        for (int nt = 0; nt < 8; nt++) {
            int p = ph * 64 + nt * 8 + (lane & 3) * 2;
            int oh = h0 + (p >> 5), ow = w0 + (p & 31);
#pragma unroll
            for (int hf = 0; hf < 2; hf++) {
                int oc = cr + t * 16 + hf * 8;
                float2 v = make_float2(oacc[t][nt][hf * 2 + 0], oacc[t][nt][hf * 2 + 1]);
                *(float2*)(out + ((size_t)b * 64 + oc) * HWn + oh * Wn + ow) = v;
            }
        }
    }
}

// ============================================================
// launch
// ============================================================
extern "C" void kernel_launch(void* const* d_in, const int* in_sizes, int n_in,
                              void* d_out, int out_size)
{
    const float* x      = (const float*)d_in[0];
    const float* ref    = (const float*)d_in[1];
    const float* w_cd   = (const float*)d_in[2];
    const float* b_cd   = (const float*)d_in[3];
    const float* w_p    = (const float*)d_in[4];
    const float* b_p    = (const float*)d_in[5];
    const float* w_m    = (const float*)d_in[6];
    const float* b_m    = (const float*)d_in[7];
    const float* w_c    = (const float*)d_in[8];
    const float* b_c    = (const float*)d_in[9];
    const float* w_conv = (const float*)d_in[10];
    float* out = (float*)d_out;

    (void)in_sizes; (void)n_in; (void)out_size;

    size_t smem2 = (size_t)(576 * 28) * sizeof(float);   // 64512 B, 3 CTAs/SM
    cudaFuncSetAttribute(k_offmod, cudaFuncAttributeMaxDynamicSharedMemorySize, (int)smem2);
    cudaFuncSetAttribute(k_main,   cudaFuncAttributeMaxDynamicSharedMemorySize, SMEM_MAIN_BYTES);

    int prep_elems = 9 * 64 * 288 + 9 * 64 * 32;
    k_prep<<<(prep_elems + 255) / 256, 256>>>(w_c, w_conv);
    k_fused<<<(Bn * HWn) / 256, 256>>>(x, ref, w_cd, b_cd);

    dim3 grid(Wn / TW, Hn / TH, Bn);   // (4, 16, 4)
    k_offmod<<<grid, 256, smem2>>>(w_p, b_p, w_m, b_m);
    k_main<<<grid, 256, SMEM_MAIN_BYTES>>>(x, b_c, out);
}

// round 15
// speedup vs baseline: 2.1756x; 1.0660x over previous
#include <cuda_runtime.h>
#include <cuda_bf16.h>
#include <math.h>
#include <stdint.h>

typedef uint32_t u32;

// Problem constants
#define Bn   4
#define Cn   64
#define Hn   128
#define Wn   128
#define HWn  16384
#define TH   8
#define TW   32
#define HALO_H 10
#define HALO_W 34
#define HCH  (HALO_H * HALO_W)          // 340
#define HALO_SZ (Cn * HCH)              // 21760 words

#define NT   512                         // threads per CTA (16 warps)

// k_main dynamic smem byte offsets
#define OFF_FSP  0                      // 21760 u32 = 87040
#define OFF_BH   87040                  // 32 x 264 u32 = 33792 (im2col hi / vbuf hi)
#define OFF_BL   120832                 // 33792 (lo)
#define OFF_A    154624                 // 2 x (64 x 44 u32 hi + same lo) = 45056
#define OFF_META 199680                 // 256 x 9 floats = 9216
#define OFF_TBL  208896                 // 288 u32 = 1152
#define SMEM_MAIN_BYTES 210048

#define BSTR 264                        // B row stride (u32)
#define ASTR 44                         // A row stride (u32)
#define A_SEL_BYTES 22528               // one A buffer (hi 11264 + lo 11264)
#define A_LO_U32 2816                   // lo offset within buffer, in u32

// -------- device scratch (static; no runtime allocation) --------
__device__ float g_fused[Bn * Cn * HWn];
__device__ u32   g_fusedp[Bn * Cn * HWn];          // packed bf16 hi|lo<<16
__device__ float g_off[Bn * 2 * 9 * HWn];
__device__ float g_mod[Bn * 9 * HWn];
__device__ u32   g_w1hi[9 * 64 * 288];             // [(k*64+c)*288 + jp]
__device__ u32   g_w1lo[9 * 64 * 288];
__device__ u32   g_w2hi[9 * 64 * 32];              // [(k*64+oc)*32 + c2]
__device__ u32   g_w2lo[9 * 64 * 32];

// -------- helpers --------
__device__ __forceinline__ u32 pack_bf16_split(float v) {
    __nv_bfloat16 h = __float2bfloat16(v);
    __nv_bfloat16 l = __float2bfloat16(v - __bfloat162float(h));
    return (u32)__bfloat16_as_ushort(h) | ((u32)__bfloat16_as_ushort(l) << 16);
}

__device__ __forceinline__ void mma_bf16(float* c,
                                         u32 a0, u32 a1, u32 a2, u32 a3,
                                         u32 b0, u32 b1) {
    asm volatile(
        "mma.sync.aligned.m16n8k16.row.col.f32.bf16.bf16.f32 "
        "{%0,%1,%2,%3}, {%4,%5,%6,%7}, {%8,%9}, {%0,%1,%2,%3};"
        : "+f"(c[0]), "+f"(c[1]), "+f"(c[2]), "+f"(c[3])
        : "r"(a0), "r"(a1), "r"(a2), "r"(a3), "r"(b0), "r"(b1));
}

__device__ __forceinline__ float fast_tanh(float x) {
    float e = __expf(2.f * x);
    return 1.f - __fdividef(2.f, e + 1.f);
}

__device__ __forceinline__ u32 smem_u32(const void* p) {
    u32 a;
    asm("{ .reg .u64 t; cvta.to.shared.u64 t, %1; cvt.u32.u64 %0, t; }"
        : "=r"(a) : "l"(p));
    return a;
}

__device__ __forceinline__ void cp16(u32 dst_smem, const void* src) {
    asm volatile("cp.async.cg.shared.global [%0], [%1], 16;"
                 :: "r"(dst_smem), "l"(src) : "memory");
}
#define CP_COMMIT() asm volatile("cp.async.commit_group;" ::: "memory")
#define CP_WAIT1()  asm volatile("cp.async.wait_group 1;" ::: "memory")
#define CP_WAIT0()  asm volatile("cp.async.wait_group 0;" ::: "memory")

// async-stage one 64x32(u32) A block (hi+lo); 512 threads -> one shot
__device__ __forceinline__ void cp_A(u32 abase_smem, int sel,
                                     const u32* srch, const u32* srcl,
                                     int src_stride, int tid) {
    u32 dh = abase_smem + (u32)sel * A_SEL_BYTES;
    u32 dl = dh + A_LO_U32 * 4;
    int row = tid >> 3, seg = tid & 7;
    u32 doff = (u32)(row * ASTR + seg * 4) * 4;
    cp16(dh + doff, srch + row * src_stride + seg * 4);
    cp16(dl + doff, srcl + row * src_stride + seg * 4);
}

// ============================================================
// Prep (merged): split weights into bf16 hi/lo pairs
// ============================================================
__global__ void k_prep(const float* __restrict__ wc, const float* __restrict__ wconv) {
    int i = blockIdx.x * 256 + threadIdx.x;
    if (i < 9 * 64 * 288) {
        int jp = i % 288;
        int kc = i / 288;
        int c = kc & 63, k = kc >> 6;
        const float* row = wc + (size_t)(c * 9 + k) * 576;
        u32 p0 = pack_bf16_split(row[2 * jp]);
        u32 p1 = pack_bf16_split(row[2 * jp + 1]);
        g_w1hi[i] = __byte_perm(p0, p1, 0x5410);
        g_w1lo[i] = __byte_perm(p0, p1, 0x7632);
    }
    int j = i - 9 * 64 * 288;
    if (j >= 0 && j < 9 * 64 * 32) {
        int c2 = j & 31;
        int kc = j >> 5;
        int oc = kc & 63, k = kc >> 6;
        u32 p0 = pack_bf16_split(wconv[(size_t)oc * 576 + (2 * c2) * 9 + k]);
        u32 p1 = pack_bf16_split(wconv[(size_t)oc * 576 + (2 * c2 + 1) * 9 + k]);
        g_w2hi[j] = __byte_perm(p0, p1, 0x5410);
        g_w2lo[j] = __byte_perm(p0, p1, 0x7632);
    }
}

// ============================================================
// Kernel 1: fused = 1x1 conv (128->64); fp32 + packed bf16 out
// ============================================================
__global__ void __launch_bounds__(256) k_fused(
    const float* __restrict__ x, const float* __restrict__ ref,
    const float* __restrict__ wcd, const float* __restrict__ bcd)
{
    __shared__ float ws[128 * 65];
    int tid = threadIdx.x;
    for (int i = tid; i < 128 * 64; i += 256) {
        int co = i >> 7, ci = i & 127;
        ws[ci * 65 + co] = wcd[i];
    }
    __syncthreads();

    int pid = blockIdx.x * 256 + tid;
    int b = pid >> 14;
    int p = pid & (HWn - 1);

    float acc[64];
#pragma unroll
    for (int co = 0; co < 64; co++) acc[co] = bcd[co];

    const float* xb = x   + (size_t)b * Cn * HWn + p;
    const float* rb = ref + (size_t)b * Cn * HWn + p;

    for (int ci = 0; ci < 64; ci++) {
        float v = __ldg(xb + ci * HWn);
        const float* w = ws + ci * 65;
#pragma unroll
        for (int co = 0; co < 64; co++) acc[co] += v * w[co];
    }
    for (int ci = 0; ci < 64; ci++) {
        float v = __ldg(rb + ci * HWn);
        const float* w = ws + (64 + ci) * 65;
#pragma unroll
        for (int co = 0; co < 64; co++) acc[co] += v * w[co];
    }

    float* o  = g_fused  + (size_t)b * Cn * HWn + p;
    u32*   op = g_fusedp + (size_t)b * Cn * HWn + p;
#pragma unroll
    for (int co = 0; co < 64; co++) {
        o[co * HWn]  = acc[co];
        op[co * HWn] = pack_bf16_split(acc[co]);
    }
}

// ============================================================
// Kernel 2: off (18ch) + mod (9ch, sigmoid), 3x3 conv pad 1.
// ============================================================
__global__ void __launch_bounds__(256) k_offmod(
    const float* __restrict__ wp, const float* __restrict__ bp,
    const float* __restrict__ wm, const float* __restrict__ bm)
{
    extern __shared__ float ws2[];   // [576][28]

    int tid = threadIdx.x;
    int b  = blockIdx.z;
    int h0 = blockIdx.y * TH;
    int w0 = blockIdx.x * TW;

    for (int i = tid; i < 27 * 576; i += 256) {
        int o = i / 576, j = i - o * 576;
        float v = (o < 18) ? wp[o * 576 + j] : wm[(o - 18) * 576 + j];
        ws2[j * 28 + o] = v;
    }
    __syncthreads();

    int ly = tid >> 5, lx = tid & 31;
    int h = h0 + ly, w = w0 + lx;

    int  offp[9];
    bool valm[9];
#pragma unroll
    for (int t = 0; t < 9; t++) {
        int gh = h - 1 + t / 3, gw = w - 1 + t % 3;
        bool v = (gh >= 0 && gh < Hn && gw >= 0 && gw < Wn);
        valm[t] = v;
        offp[t] = v ? (gh * Wn + gw) : 0;
    }

    const float* fb = g_fused + (size_t)b * Cn * HWn;

    float acc[27];
#pragma unroll
    for (int o = 0; o < 27; o++) acc[o] = (o < 18) ? bp[o] : bm[o - 18];

    for (int ic = 0; ic < 64; ic++) {
        const float* base = fb + ic * HWn;
        float u[9];
#pragma unroll
        for (int t = 0; t < 9; t++)
            u[t] = valm[t] ? __ldg(base + offp[t]) : 0.f;
#pragma unroll
        for (int t = 0; t < 9; t++) {
            const float* wv = ws2 + (ic * 9 + t) * 28;
#pragma unroll
            for (int o = 0; o < 27; o++) acc[o] += u[t] * wv[o];
        }
    }

    int pix = h * Wn + w;
#pragma unroll
    for (int o = 0; o < 18; o++)
        g_off[((size_t)b * 18 + o) * HWn + pix] = acc[o];
#pragma unroll
    for (int o = 0; o < 9; o++)
        g_mod[((size_t)b * 9 + o) * HWn + pix] = 1.f / (1.f + expf(-acc[18 + o]));
}

// ============================================================
// Kernel 3: main — bf16 HMMA (3-split) GEMMs, 512 threads,
// warp tile 16 m-rows x 64 pixels (16 warps = 4 m x 4 pix quarters).
// ============================================================
__global__ void __launch_bounds__(NT, 1) k_main(
    const float* __restrict__ x, const float* __restrict__ bc,
    float* __restrict__ out)
{
    extern __shared__ unsigned char smc[];
    u32*   fsp  = (u32*)(smc + OFF_FSP);
    u32*   bhw  = (u32*)(smc + OFF_BH);
    u32*   blw  = (u32*)(smc + OFF_BL);
    float* meta = (float*)(smc + OFF_META);
    u32*   tbl  = (u32*)(smc + OFF_TBL);

    u32 abase = smem_u32(smc) + OFF_A;

    int tid  = threadIdx.x;
    int warp = tid >> 5;
    int lane = tid & 31;
    int b  = blockIdx.z;
    int h0 = blockIdx.y * TH;
    int w0 = blockIdx.x * TW;

    int mq = warp & 3;          // m quarter: rows mq*16 .. +15
    int ph = warp >> 2;         // pixel quarter: ph*64 .. +63

    // --- halo load (packed bf16 fused) ---
    const u32* fb = g_fusedp + (size_t)b * Cn * HWn;
    for (int i = tid; i < HALO_SZ; i += NT) {
        int ic = i / HCH;
        int rr = (i / HALO_W) % HALO_H;
        int cc = i % HALO_W;
        int gh = h0 - 1 + rr, gw = w0 - 1 + cc;
        u32 v = 0;
        if (gh >= 0 && gh < Hn && gw >= 0 && gw < Wn)
            v = fb[ic * HWn + gh * Wn + gw];
        fsp[i] = v;
    }
    // --- im2col offset table ---
    if (tid < 288) {
        int j0 = 2 * tid, j1 = 2 * tid + 1;
        int ic0 = j0 / 9, t0 = j0 - ic0 * 9;
        int ic1 = j1 / 9, t1 = j1 - ic1 * 9;
        u32 o0 = (u32)(ic0 * HCH + (t0 / 3) * HALO_W + (t0 % 3));
        u32 o1 = (u32)(ic1 * HCH + (t1 / 3) * HALO_W + (t1 % 3));
        tbl[tid] = o0 | (o1 << 16);
    }

    // meta pixel for threads 0..255
    int mpx = tid & 255;
    int hh = h0 + (mpx >> 5), ww = w0 + (mpx & 31);
    int pix = hh * Wn + ww;
    // im2col: pixel + row-half for the build
    int bpix = tid & 255;
    int bhalf = tid >> 8;                 // 0 or 1: rows bhalf*16 .. +15
    int bp = (bpix >> 5) * HALO_W + (bpix & 31);

    const float* xb = x + (size_t)b * Cn * HWn;

    int cr = mq * 16 + (lane >> 2);       // this thread's first channel row
    const float* xc0 = xb + cr * HWn;
    const float* xc1 = xb + (cr + 8) * HWn;

    float oacc[8][4];
#pragma unroll
    for (int nt = 0; nt < 8; nt++)
#pragma unroll
        for (int e = 0; e < 4; e++) oacc[nt][e] = 0.f;

    // prologue: prefetch A1(k=0, s=0) into buffer 0
    int sel = 0;
    cp_A(abase, 0, g_w1hi, g_w1lo, 288, tid);
    CP_COMMIT();

    for (int k = 0; k < 9; k++) {
        // ---- sampling metadata (threads 0..255, one pixel each) ----
        if (tid < 256) {
            float offx = g_off[((size_t)b * 18 + k) * HWn + pix];
            float offy = g_off[((size_t)b * 18 + 9 + k) * HWn + pix];
            float modk = g_mod[((size_t)b * 9 + k) * HWn + pix];

            float px = (float)(hh + 1) + offx + (float)(k / 3 - 1);
            float py = (float)(ww + 1) + offy + (float)(k % 3 - 1);
            float fx = floorf(px), fy = floorf(py);
            float qltx = fminf(fmaxf(fx,       0.f), 129.f);
            float qlty = fminf(fmaxf(fy,       0.f), 129.f);
            float qrbx = fminf(fmaxf(fx + 1.f, 0.f), 129.f);
            float qrby = fminf(fmaxf(fy + 1.f, 0.f), 129.f);
            float sx = fminf(fmaxf(px, 0.f), 129.f);
            float sy = fminf(fmaxf(py, 0.f), 129.f);
            float glt = (1.f + qltx - sx) * (1.f + qlty - sy);
            float grb = (1.f - qrbx + sx) * (1.f - qrby + sy);
            float glb = (1.f + qltx - sx) * (1.f - qrby + sy);
            float grt = (1.f - qrbx + sx) * (1.f + qlty - sy);

            int ix0 = (int)qltx, iy0 = (int)qlty;
            int ix1 = (int)qrbx, iy1 = (int)qrby;
            bool vx0 = (ix0 >= 1 && ix0 <= 128), vy0 = (iy0 >= 1 && iy0 <= 128);
            bool vx1 = (ix1 >= 1 && ix1 <= 128), vy1 = (iy1 >= 1 && iy1 <= 128);
            bool v00 = vx0 && vy0, v11 = vx1 && vy1;
            bool v01 = vx0 && vy1, v10 = vx1 && vy0;
            int o00 = v00 ? ((ix0 - 1) * Wn + (iy0 - 1)) : 0;
            int o11 = v11 ? ((ix1 - 1) * Wn + (iy1 - 1)) : 0;
            int o01 = v01 ? ((ix0 - 1) * Wn + (iy1 - 1)) : 0;
            int o10 = v10 ? ((ix1 - 1) * Wn + (iy0 - 1)) : 0;

            float* mt = meta + mpx * 9;
            mt[0] = v00 ? glt : 0.f;
            mt[1] = v11 ? grb : 0.f;
            mt[2] = v01 ? glb : 0.f;
            mt[3] = v10 ? grt : 0.f;
            mt[4] = __uint_as_float((u32)o00 | ((u32)o11 << 16));
            mt[5] = __uint_as_float((u32)o01 | ((u32)o10 << 16));
            mt[6] = modk;
        }

        // ---- GEMM1: conv[64 x 256], K=576 in 9 chunks of 64 ----
        float acc[8][4];
#pragma unroll
        for (int nt = 0; nt < 8; nt++)
#pragma unroll
            for (int e = 0; e < 4; e++) acc[nt][e] = 0.f;

        for (int s = 0; s < 9; s++) {
            __syncthreads();   // prev users of B done

            // build im2col pairs via offset table (each thread: 16 rows)
            {
                const u32* ts = tbl + s * 32 + bhalf * 16;
#pragma unroll
                for (int jj = 0; jj < 16; jj++) {
                    u32 oo = ts[jj];
                    u32 w0v = fsp[(oo & 0xFFFF) + bp];
                    u32 w1v = fsp[(oo >> 16) + bp];
                    int jp = bhalf * 16 + jj;
                    bhw[jp * BSTR + bpix] = __byte_perm(w0v, w1v, 0x5410);
                    blw[jp * BSTR + bpix] = __byte_perm(w0v, w1v, 0x7632);
                }
            }
            // prefetch next A block
            if (s < 8)
                cp_A(abase, sel ^ 1,
                     g_w1hi + (size_t)(k * 64) * 288 + (s + 1) * 32,
                     g_w1lo + (size_t)(k * 64) * 288 + (s + 1) * 32, 288, tid);
            else
                cp_A(abase, sel ^ 1,
                     g_w2hi + (size_t)(k * 64) * 32,
                     g_w2lo + (size_t)(k * 64) * 32, 32, tid);
            CP_COMMIT();
            CP_WAIT1();
            __syncthreads();

            const u32* ahw = (const u32*)(smc + OFF_A + sel * A_SEL_BYTES);
            const u32* alw = ahw + A_LO_U32;

#pragma unroll
            for (int ks = 0; ks < 4; ks++) {
                int k2 = ks * 8 + (lane & 3);
                int rb = (mq * 16 + (lane >> 2)) * ASTR;
                u32 Ah0 = ahw[rb + k2];
                u32 Ah1 = ahw[rb + 8 * ASTR + k2];
                u32 Ah2 = ahw[rb + k2 + 4];
                u32 Ah3 = ahw[rb + 8 * ASTR + k2 + 4];
                u32 Al0 = alw[rb + k2];
                u32 Al1 = alw[rb + 8 * ASTR + k2];
                u32 Al2 = alw[rb + k2 + 4];
                u32 Al3 = alw[rb + 8 * ASTR + k2 + 4];
                int nb = ph * 64 + (lane >> 2);
#pragma unroll
                for (int nt = 0; nt < 8; nt++) {
                    int n = nb + nt * 8;
                    u32 b0h = bhw[k2 * BSTR + n];
                    u32 b1h = bhw[(k2 + 4) * BSTR + n];
                    u32 b0l = blw[k2 * BSTR + n];
                    u32 b1l = blw[(k2 + 4) * BSTR + n];
                    mma_bf16(acc[nt], Ah0, Ah1, Ah2, Ah3, b0h, b1h);
                    mma_bf16(acc[nt], Ah0, Ah1, Ah2, Ah3, b0l, b1l);
                    mma_bf16(acc[nt], Al0, Al1, Al2, Al3, b0h, b1h);
                }
            }
            sel ^= 1;
        }

        __syncthreads();   // GEMM1 reads of B complete

        // prefetch next tap's first A1 chunk; ensure this tap's W2 landed
        if (k < 8) {
            cp_A(abase, sel ^ 1,
                 g_w1hi + (size_t)((k + 1) * 64) * 288,
                 g_w1lo + (size_t)((k + 1) * 64) * 288, 288, tid);
            CP_COMMIT();
            CP_WAIT1();
        } else {
            CP_WAIT0();
        }

        // ---- epilogue: bias + tanh + bilinear + mod -> vbuf (reuses B) ----
        {
            float bias0 = bc[cr * 9 + k];
            float bias1 = bc[(cr + 8) * 9 + k];

#pragma unroll
            for (int nt = 0; nt < 8; nt++) {
                int pA = ph * 64 + nt * 8 + (lane & 3) * 2;
#pragma unroll
                for (int hf = 0; hf < 2; hf++) {
                    int c  = cr + hf * 8;
                    int c2 = c >> 1;
                    u32 halfoff = (u32)(c & 1) << 1;
                    const float* xc = hf ? xc1 : xc0;
                    float bias = hf ? bias1 : bias0;
#pragma unroll
                    for (int e = 0; e < 2; e++) {
                        int p = pA + e;
                        const float* mt = meta + p * 9;
                        u32 pk0 = __float_as_uint(mt[4]);
                        u32 pk1 = __float_as_uint(mt[5]);
                        float pos = mt[0] * __ldg(xc + (pk0 & 0xFFFF))
                                  + mt[1] * __ldg(xc + (pk0 >> 16))
                                  + mt[2] * __ldg(xc + (pk1 & 0xFFFF))
                                  + mt[3] * __ldg(xc + (pk1 >> 16));
                        float conv = acc[nt][hf * 2 + e] + bias;
                        float v = (fast_tanh(conv) + pos) * mt[6];
                        u32 pk = pack_bf16_split(v);
                        u32 woff = (u32)(c2 * BSTR + p) << 2;
                        *(unsigned short*)(smc + OFF_BH + woff + halfoff)
                            = (unsigned short)(pk & 0xFFFF);
                        *(unsigned short*)(smc + OFF_BL + woff + halfoff)
                            = (unsigned short)(pk >> 16);
                    }
                }
            }
        }
        __syncthreads();   // vbuf visible (W2 already waited)

        // ---- GEMM2: oacc += W2[64 x 64] @ v[64 x 256] ----
        {
            const u32* ahw = (const u32*)(smc + OFF_A + sel * A_SEL_BYTES);
            const u32* alw = ahw + A_LO_U32;
#pragma unroll
            for (int ks = 0; ks < 4; ks++) {
                int k2 = ks * 8 + (lane & 3);
                int rb = (mq * 16 + (lane >> 2)) * ASTR;
                u32 Ah0 = ahw[rb + k2];
                u32 Ah1 = ahw[rb + 8 * ASTR + k2];
                u32 Ah2 = ahw[rb + k2 + 4];
                u32 Ah3 = ahw[rb + 8 * ASTR + k2 + 4];
                u32 Al0 = alw[rb + k2];
                u32 Al1 = alw[rb + 8 * ASTR + k2];
                u32 Al2 = alw[rb + k2 + 4];
                u32 Al3 = alw[rb + 8 * ASTR + k2 + 4];
                int nb = ph * 64 + (lane >> 2);
#pragma unroll
                for (int nt = 0; nt < 8; nt++) {
                    int n = nb + nt * 8;
                    u32 b0h = bhw[k2 * BSTR + n];
                    u32 b1h = bhw[(k2 + 4) * BSTR + n];
                    u32 b0l = blw[k2 * BSTR + n];
                    u32 b1l = blw[(k2 + 4) * BSTR + n];
                    mma_bf16(oacc[nt], Ah0, Ah1, Ah2, Ah3, b0h, b1h);
                    mma_bf16(oacc[nt], Ah0, Ah1, Ah2, Ah3, b0l, b1l);
                    mma_bf16(oacc[nt], Al0, Al1, Al2, Al3, b0h, b1h);
                }
            }
        }
        sel ^= 1;
    }

    // ---- store output ----
#pragma unroll
    for (int nt = 0; nt < 8; nt++) {
        int p = ph * 64 + nt * 8 + (lane & 3) * 2;
        int oh = h0 + (p >> 5), ow = w0 + (p & 31);
#pragma unroll
        for (int hf = 0; hf < 2; hf++) {
            int oc = cr + hf * 8;
            float2 v = make_float2(oacc[nt][hf * 2 + 0], oacc[nt][hf * 2 + 1]);
            *(float2*)(out + ((size_t)b * 64 + oc) * HWn + oh * Wn + ow) = v;
        }
    }
}

// ============================================================
// launch
// ============================================================
extern "C" void kernel_launch(void* const* d_in, const int* in_sizes, int n_in,
                              void* d_out, int out_size)
{
    const float* x      = (const float*)d_in[0];
    const float* ref    = (const float*)d_in[1];
    const float* w_cd   = (const float*)d_in[2];
    const float* b_cd   = (const float*)d_in[3];
    const float* w_p    = (const float*)d_in[4];
    const float* b_p    = (const float*)d_in[5];
    const float* w_m    = (const float*)d_in[6];
    const float* b_m    = (const float*)d_in[7];
    const float* w_c    = (const float*)d_in[8];
    const float* b_c    = (const float*)d_in[9];
    const float* w_conv = (const float*)d_in[10];
    float* out = (float*)d_out;

    (void)in_sizes; (void)n_in; (void)out_size;

    size_t smem2 = (size_t)(576 * 28) * sizeof(float);   // 64512 B
    cudaFuncSetAttribute(k_offmod, cudaFuncAttributeMaxDynamicSharedMemorySize, (int)smem2);
    cudaFuncSetAttribute(k_main,   cudaFuncAttributeMaxDynamicSharedMemorySize, SMEM_MAIN_BYTES);

    int prep_elems = 9 * 64 * 288 + 9 * 64 * 32;
    k_prep<<<(prep_elems + 255) / 256, 256>>>(w_c, w_conv);
    k_fused<<<(Bn * HWn) / 256, 256>>>(x, ref, w_cd, b_cd);

    dim3 grid(Wn / TW, Hn / TH, Bn);   // (4, 16, 4)
    k_offmod<<<grid, 256, smem2>>>(w_p, b_p, w_m, b_m);
    k_main<<<grid, NT, SMEM_MAIN_BYTES>>>(x, b_c, out);
}

// round 17
// speedup vs baseline: 2.8769x; 1.3223x over previous
#include <cuda_runtime.h>
#include <cuda_fp16.h>
#include <math.h>
#include <stdint.h>

typedef uint32_t u32;
typedef unsigned short u16;

// Problem constants
#define Bn   4
#define Cn   64
#define Hn   128
#define Wn   128
#define HWn  16384
#define TH   8
#define TW   32
#define HALO_H 10
#define HALO_W 34
#define HCH  (HALO_H * HALO_W)          // 340
#define HALO_SZ (Cn * HCH)              // 21760 elements

#define NT   256

// k_conv dynamic smem byte offsets
#define OFF_FSH  0                      // 21760 u16 = 43520
#define OFF_B    43520                  // 32 x 264 u32 = 33792 (im2col / vbuf)
#define OFF_A    77312                  // 2 x 9216 = 18432
#define OFF_META 95744                  // 256 x 8 floats = 8192
#define OFF_TBL  103936                 // 288 u32 = 1152
#define SMEM_CONV_BYTES 105088          // -> 2 CTAs/SM

#define BSTR 264                        // B row stride (u32)
#define VSTR 264                        // vbuf row stride (u16)  [FIX: was 2*BSTR]
#define ASTR 36                         // A row stride (u32)
#define A_SEL_BYTES 9216

// k_gemm2 smem
#define ASTR2 292
#define OFF2_A 0                        // 64 x 292 u32 = 74752
#define OFF2_B 74752                    // 32 x 264 u32 = 33792
#define SMEM_G2_BYTES 108544

// -------- device scratch (static; no runtime allocation) --------
__device__ float g_fused[Bn * Cn * HWn];
__device__ u16   g_fusedh[Bn * Cn * HWn];          // fp16 fused
__device__ float g_off[Bn * 2 * 9 * HWn];
__device__ float g_mod[Bn * 9 * HWn];
__device__ u32   g_w1[9 * 64 * 288];               // [(k*64+c)*288 + jp] fp16 pair
__device__ u32   g_w2[64 * 288];                   // [oc*288 + k*32 + c2] fp16 pair
__device__ u32   g_v[(size_t)Bn * 288 * HWn];      // v fp16 pairs [b][k*32+c2][pix]

// -------- helpers --------
__device__ __forceinline__ u16 f2h(float v) {
    return __half_as_ushort(__float2half_rn(v));
}

__device__ __forceinline__ void mma_fp16(float* c,
                                         u32 a0, u32 a1, u32 a2, u32 a3,
                                         u32 b0, u32 b1) {
    asm volatile(
        "mma.sync.aligned.m16n8k16.row.col.f32.f16.f16.f32 "
        "{%0,%1,%2,%3}, {%4,%5,%6,%7}, {%8,%9}, {%0,%1,%2,%3};"
        : "+f"(c[0]), "+f"(c[1]), "+f"(c[2]), "+f"(c[3])
        : "r"(a0), "r"(a1), "r"(a2), "r"(a3), "r"(b0), "r"(b1));
}

__device__ __forceinline__ float fast_tanh(float x) {
    float e = __expf(2.f * x);
    return 1.f - __fdividef(2.f, e + 1.f);
}

__device__ __forceinline__ u32 smem_u32(const void* p) {
    u32 a;
    asm("{ .reg .u64 t; cvta.to.shared.u64 t, %1; cvt.u32.u64 %0, t; }"
        : "=r"(a) : "l"(p));
    return a;
}

__device__ __forceinline__ void cp16(u32 dst_smem, const void* src) {
    asm volatile("cp.async.cg.shared.global [%0], [%1], 16;"
                 :: "r"(dst_smem), "l"(src) : "memory");
}
#define CP_COMMIT() asm volatile("cp.async.commit_group;" ::: "memory")
#define CP_WAIT1()  asm volatile("cp.async.wait_group 1;" ::: "memory")
#define CP_WAIT0()  asm volatile("cp.async.wait_group 0;" ::: "memory")

// stage one 64x32(u32) A block into buffer `sel` (256 threads, 2 cp16 each)
__device__ __forceinline__ void cp_A(u32 abase_smem, int sel,
                                     const u32* src, int src_stride, int tid) {
    u32 d = abase_smem + (u32)sel * A_SEL_BYTES;
#pragma unroll
    for (int part = 0; part < 2; part++) {
        int idx = part * 256 + tid;
        int row = idx >> 3, seg = idx & 7;
        cp16(d + (u32)(row * ASTR + seg * 4) * 4, src + row * src_stride + seg * 4);
    }
}

// ============================================================
// Prep: fp16 pair tables for W1 (conv) and W2 (final contraction)
// ============================================================
__global__ void k_prep(const float* __restrict__ wc, const float* __restrict__ wconv) {
    int i = blockIdx.x * 256 + threadIdx.x;
    if (i < 9 * 64 * 288) {
        int jp = i % 288;
        int kc = i / 288;
        int c = kc & 63, k = kc >> 6;
        const float* row = wc + (size_t)(c * 9 + k) * 576;
        g_w1[i] = (u32)f2h(row[2 * jp]) | ((u32)f2h(row[2 * jp + 1]) << 16);
    }
    int j = i - 9 * 64 * 288;
    if (j >= 0 && j < 64 * 288) {
        int col = j % 288;
        int oc  = j / 288;
        int k = col >> 5, c2 = col & 31;
        g_w2[j] = (u32)f2h(wconv[(size_t)oc * 576 + (2 * c2) * 9 + k])
                | ((u32)f2h(wconv[(size_t)oc * 576 + (2 * c2 + 1) * 9 + k]) << 16);
    }
}

// ============================================================
// Kernel 1: fused = 1x1 conv (128->64); fp32 + fp16 out
// ============================================================
__global__ void __launch_bounds__(256) k_fused(
    const float* __restrict__ x, const float* __restrict__ ref,
    const float* __restrict__ wcd, const float* __restrict__ bcd)
{
    __shared__ float ws[128 * 65];
    int tid = threadIdx.x;
    for (int i = tid; i < 128 * 64; i += 256) {
        int co = i >> 7, ci = i & 127;
        ws[ci * 65 + co] = wcd[i];
    }
    __syncthreads();

    int pid = blockIdx.x * 256 + tid;
    int b = pid >> 14;
    int p = pid & (HWn - 1);

    float acc[64];
#pragma unroll
    for (int co = 0; co < 64; co++) acc[co] = bcd[co];

    const float* xb = x   + (size_t)b * Cn * HWn + p;
    const float* rb = ref + (size_t)b * Cn * HWn + p;

    for (int ci = 0; ci < 64; ci++) {
        float v = __ldg(xb + ci * HWn);
        const float* w = ws + ci * 65;
#pragma unroll
        for (int co = 0; co < 64; co++) acc[co] += v * w[co];
    }
    for (int ci = 0; ci < 64; ci++) {
        float v = __ldg(rb + ci * HWn);
        const float* w = ws + (64 + ci) * 65;
#pragma unroll
        for (int co = 0; co < 64; co++) acc[co] += v * w[co];
    }

    float* o  = g_fused  + (size_t)b * Cn * HWn + p;
    u16*   oh = g_fusedh + (size_t)b * Cn * HWn + p;
#pragma unroll
    for (int co = 0; co < 64; co++) {
        o[co * HWn]  = acc[co];
        oh[co * HWn] = f2h(acc[co]);
    }
}

// ============================================================
// Kernel 2: off (18ch) + mod (9ch, sigmoid), 3x3 conv pad 1.
// ============================================================
__global__ void __launch_bounds__(256) k_offmod(
    const float* __restrict__ wp, const float* __restrict__ bp,
    const float* __restrict__ wm, const float* __restrict__ bm)
{
    extern __shared__ float ws2[];   // [576][28]

    int tid = threadIdx.x;
    int b  = blockIdx.z;
    int h0 = blockIdx.y * TH;
    int w0 = blockIdx.x * TW;

    for (int i = tid; i < 27 * 576; i += 256) {
        int o = i / 576, j = i - o * 576;
        float v = (o < 18) ? wp[o * 576 + j] : wm[(o - 18) * 576 + j];
        ws2[j * 28 + o] = v;
    }
    __syncthreads();

    int ly = tid >> 5, lx = tid & 31;
    int h = h0 + ly, w = w0 + lx;

    int  offp[9];
    bool valm[9];
#pragma unroll
    for (int t = 0; t < 9; t++) {
        int gh = h - 1 + t / 3, gw = w - 1 + t % 3;
        bool v = (gh >= 0 && gh < Hn && gw >= 0 && gw < Wn);
        valm[t] = v;
        offp[t] = v ? (gh * Wn + gw) : 0;
    }

    const float* fb = g_fused + (size_t)b * Cn * HWn;

    float acc[27];
#pragma unroll
    for (int o = 0; o < 27; o++) acc[o] = (o < 18) ? bp[o] : bm[o - 18];

    for (int ic = 0; ic < 64; ic++) {
        const float* base = fb + ic * HWn;
        float u[9];
#pragma unroll
        for (int t = 0; t < 9; t++)
            u[t] = valm[t] ? __ldg(base + offp[t]) : 0.f;
#pragma unroll
        for (int t = 0; t < 9; t++) {
            const float* wv = ws2 + (ic * 9 + t) * 28;
#pragma unroll
            for (int o = 0; o < 27; o++) acc[o] += u[t] * wv[o];
        }
    }

    int pix = h * Wn + w;
#pragma unroll
    for (int o = 0; o < 18; o++)
        g_off[((size_t)b * 18 + o) * HWn + pix] = acc[o];
#pragma unroll
    for (int o = 0; o < 9; o++)
        g_mod[((size_t)b * 9 + o) * HWn + pix] = 1.f / (1.f + expf(-acc[18 + o]));
}

// ============================================================
// Kernel 3: conv GEMM (fp16 single-term HMMA) + deform epilogue -> g_v
// 256 threads, 8 warps: warp = 32 m-rows x 64 pixels. 2 CTAs/SM.
// ============================================================
__global__ void __launch_bounds__(NT, 2) k_conv(
    const float* __restrict__ x, const float* __restrict__ bc)
{
    extern __shared__ unsigned char smc[];
    u16*   fsh  = (u16*)(smc + OFF_FSH);
    u32*   bb   = (u32*)(smc + OFF_B);
    u16*   vb16 = (u16*)(smc + OFF_B);   // vbuf alias: 64 rows x VSTR u16
    float* meta = (float*)(smc + OFF_META);
    u32*   tbl  = (u32*)(smc + OFF_TBL);

    u32 abase = smem_u32(smc) + OFF_A;

    int tid  = threadIdx.x;
    int warp = tid >> 5;
    int lane = tid & 31;
    int b  = blockIdx.z;
    int h0 = blockIdx.y * TH;
    int w0 = blockIdx.x * TW;

    int mp = warp & 1;          // m half: rows mp*32 .. +31 (2 m16 tiles)
    int pq = warp >> 1;         // pixel quarter: pq*64 .. +63

    // --- halo load (fp16 fused) ---
    const u16* fb = g_fusedh + (size_t)b * Cn * HWn;
    for (int i = tid; i < HALO_SZ; i += NT) {
        int ic = i / HCH;
        int rr = (i / HALO_W) % HALO_H;
        int cc = i % HALO_W;
        int gh = h0 - 1 + rr, gw = w0 - 1 + cc;
        u16 v = 0;
        if (gh >= 0 && gh < Hn && gw >= 0 && gw < Wn)
            v = fb[ic * HWn + gh * Wn + gw];
        fsh[i] = v;
    }
    // --- im2col offset table ---
    for (int i = tid; i < 288; i += NT) {
        int j0 = 2 * i, j1 = 2 * i + 1;
        int ic0 = j0 / 9, t0 = j0 - ic0 * 9;
        int ic1 = j1 / 9, t1 = j1 - ic1 * 9;
        u32 o0 = (u32)(ic0 * HCH + (t0 / 3) * HALO_W + (t0 % 3));
        u32 o1 = (u32)(ic1 * HCH + (t1 / 3) * HALO_W + (t1 % 3));
        tbl[i] = o0 | (o1 << 16);
    }

    int hh = h0 + (tid >> 5), ww = w0 + (tid & 31);
    int pix = hh * Wn + ww;
    int bp = (tid >> 5) * HALO_W + (tid & 31);
    const float* xb = x + (size_t)b * Cn * HWn;

    int cr = mp * 32 + (lane >> 2);       // first channel row (tiles at +0,+16; hf +8)

    // prologue: prefetch A1(k=0, s=0)
    int sel = 0;
    cp_A(abase, 0, g_w1, 288, tid);
    CP_COMMIT();

    for (int k = 0; k < 9; k++) {
        // ---- sampling metadata (one pixel per thread) ----
        {
            float offx = g_off[((size_t)b * 18 + k) * HWn + pix];
            float offy = g_off[((size_t)b * 18 + 9 + k) * HWn + pix];
            float modk = g_mod[((size_t)b * 9 + k) * HWn + pix];

            float px = (float)(hh + 1) + offx + (float)(k / 3 - 1);
            float py = (float)(ww + 1) + offy + (float)(k % 3 - 1);
            float fx = floorf(px), fy = floorf(py);
            float qltx = fminf(fmaxf(fx,       0.f), 129.f);
            float qlty = fminf(fmaxf(fy,       0.f), 129.f);
            float qrbx = fminf(fmaxf(fx + 1.f, 0.f), 129.f);
            float qrby = fminf(fmaxf(fy + 1.f, 0.f), 129.f);
            float sx = fminf(fmaxf(px, 0.f), 129.f);
            float sy = fminf(fmaxf(py, 0.f), 129.f);
            float glt = (1.f + qltx - sx) * (1.f + qlty - sy);
            float grb = (1.f - qrbx + sx) * (1.f - qrby + sy);
            float glb = (1.f + qltx - sx) * (1.f - qrby + sy);
            float grt = (1.f - qrbx + sx) * (1.f + qlty - sy);

            int ix0 = (int)qltx, iy0 = (int)qlty;
            int ix1 = (int)qrbx, iy1 = (int)qrby;
            bool vx0 = (ix0 >= 1 && ix0 <= 128), vy0 = (iy0 >= 1 && iy0 <= 128);
            bool vx1 = (ix1 >= 1 && ix1 <= 128), vy1 = (iy1 >= 1 && iy1 <= 128);
            bool v00 = vx0 && vy0, v11 = vx1 && vy1;
            bool v01 = vx0 && vy1, v10 = vx1 && vy0;
            int o00 = v00 ? ((ix0 - 1) * Wn + (iy0 - 1)) : 0;
            int o11 = v11 ? ((ix1 - 1) * Wn + (iy1 - 1)) : 0;
            int o01 = v01 ? ((ix0 - 1) * Wn + (iy1 - 1)) : 0;
            int o10 = v10 ? ((ix1 - 1) * Wn + (iy0 - 1)) : 0;

            float* mt = meta + tid * 8;
            mt[0] = v00 ? glt : 0.f;
            mt[1] = v11 ? grb : 0.f;
            mt[2] = v01 ? glb : 0.f;
            mt[3] = v10 ? grt : 0.f;
            mt[4] = __uint_as_float((u32)o00 | ((u32)o11 << 16));
            mt[5] = __uint_as_float((u32)o01 | ((u32)o10 << 16));
            mt[6] = modk;
        }

        // ---- GEMM1: conv[64 x 256], K=576 in 9 chunks of 64 ----
        float acc[2][8][4];
#pragma unroll
        for (int t = 0; t < 2; t++)
#pragma unroll
            for (int nt = 0; nt < 8; nt++)
#pragma unroll
                for (int e = 0; e < 4; e++) acc[t][nt][e] = 0.f;

        for (int s = 0; s < 9; s++) {
            __syncthreads();   // prev users of B done

            // build im2col (each thread: 32 pair-rows at its pixel)
            {
                const u32* ts = tbl + s * 32;
#pragma unroll 8
                for (int jp = 0; jp < 32; jp++) {
                    u32 oo = ts[jp];
                    u32 h0v = fsh[(oo & 0xFFFF) + bp];
                    u32 h1v = fsh[(oo >> 16) + bp];
                    bb[jp * BSTR + tid] = h0v | (h1v << 16);
                }
            }
            // prefetch next A block
            bool pf = true;
            if (s < 8)
                cp_A(abase, sel ^ 1, g_w1 + (size_t)(k * 64) * 288 + (s + 1) * 32, 288, tid);
            else if (k < 8)
                cp_A(abase, sel ^ 1, g_w1 + (size_t)((k + 1) * 64) * 288, 288, tid);
            else
                pf = false;
            if (pf) { CP_COMMIT(); CP_WAIT1(); } else { CP_WAIT0(); }
            __syncthreads();

            const u32* aw = (const u32*)(smc + OFF_A + sel * A_SEL_BYTES);

#pragma unroll
            for (int ks = 0; ks < 4; ks++) {
                int k2 = ks * 8 + (lane & 3);
                u32 A0[2], A1[2], A2[2], A3[2];
#pragma unroll
                for (int t = 0; t < 2; t++) {
                    int rb = (mp * 32 + t * 16 + (lane >> 2)) * ASTR;
                    A0[t] = aw[rb + k2];
                    A1[t] = aw[rb + 8 * ASTR + k2];
                    A2[t] = aw[rb + k2 + 4];
                    A3[t] = aw[rb + 8 * ASTR + k2 + 4];
                }
                int nb = pq * 64 + (lane >> 2);
#pragma unroll
                for (int nt = 0; nt < 8; nt++) {
                    int n = nb + nt * 8;
                    u32 b0 = bb[k2 * BSTR + n];
                    u32 b1 = bb[(k2 + 4) * BSTR + n];
#pragma unroll
                    for (int t = 0; t < 2; t++)
                        mma_fp16(acc[t][nt], A0[t], A1[t], A2[t], A3[t], b0, b1);
                }
            }
            sel ^= 1;
        }

        __syncthreads();   // GEMM1 reads of B complete

        // ---- epilogue: bias + tanh + bilinear + mod -> vbuf (fp16) ----
        {
#pragma unroll
            for (int t = 0; t < 2; t++) {
                float bias0 = bc[(cr + t * 16) * 9 + k];
                float bias1 = bc[(cr + t * 16 + 8) * 9 + k];
#pragma unroll
                for (int nt = 0; nt < 8; nt++) {
                    int pA = pq * 64 + nt * 8 + (lane & 3) * 2;
#pragma unroll
                    for (int hf = 0; hf < 2; hf++) {
                        int c = cr + t * 16 + hf * 8;
                        const float* xc = xb + c * HWn;
                        float bias = hf ? bias1 : bias0;
#pragma unroll
                        for (int e = 0; e < 2; e++) {
                            int p = pA + e;
                            const float* mt = meta + p * 8;
                            u32 pk0 = __float_as_uint(mt[4]);
                            u32 pk1 = __float_as_uint(mt[5]);
                            float pos = mt[0] * __ldg(xc + (pk0 & 0xFFFF))
                                      + mt[1] * __ldg(xc + (pk0 >> 16))
                                      + mt[2] * __ldg(xc + (pk1 & 0xFFFF))
                                      + mt[3] * __ldg(xc + (pk1 >> 16));
                            float conv = acc[t][nt][hf * 2 + e] + bias;
                            float v = (fast_tanh(conv) + pos) * mt[6];
                            vb16[c * VSTR + p] = f2h(v);
                        }
                    }
                }
            }
        }
        __syncthreads();   // vbuf complete

        // ---- flush v pairs to gmem: g_v[b][k*32+c2][pix] ----
        {
            int gp = (h0 + (tid >> 5)) * Wn + w0 + (tid & 31);
            u32* vg = g_v + ((size_t)b * 288 + k * 32) * HWn + gp;
#pragma unroll 8
            for (int c2 = 0; c2 < 32; c2++) {
                u32 lo = vb16[(2 * c2) * VSTR + tid];
                u32 hi = vb16[(2 * c2 + 1) * VSTR + tid];
                vg[(size_t)c2 * HWn] = lo | (hi << 16);
            }
        }
    }
}

// ============================================================
// Kernel 4: final contraction out[64 x 16384] = W2[64 x 576] @ v
// 512 threads, warp = 16 oc x 64 pix; CTA = 64 oc x 256 pix.
// ============================================================
__global__ void __launch_bounds__(512) k_gemm2(float* __restrict__ out)
{
    extern __shared__ unsigned char smc[];
    u32* a2 = (u32*)(smc + OFF2_A);
    u32* bb = (u32*)(smc + OFF2_B);
    u32 bbase = smem_u32(smc) + OFF2_B;

    int tid  = threadIdx.x;
    int warp = tid >> 5;
    int lane = tid & 31;
    int b   = blockIdx.z;
    int px0 = blockIdx.x * 256;

    int mq = warp & 3;          // oc quarter (16 rows)
    int pq = warp >> 2;         // pixel quarter (64)

    // stage full W2 [64][288]
    for (int i = tid; i < 64 * 288; i += 512) {
        int r = i / 288, col = i - r * 288;
        a2[r * ASTR2 + col] = g_w2[i];
    }

    float acc[8][4];
#pragma unroll
    for (int nt = 0; nt < 8; nt++)
#pragma unroll
        for (int e = 0; e < 4; e++) acc[nt][e] = 0.f;

    for (int ch = 0; ch < 9; ch++) {
        __syncthreads();
        // cp.async B chunk: 32 rows x 256 u32
        {
            const u32* src = g_v + ((size_t)b * 288 + ch * 32) * HWn + px0;
#pragma unroll
            for (int part = 0; part < 4; part++) {
                int idx = part * 512 + tid;
                int row = idx >> 6, seg = idx & 63;
                cp16(bbase + (u32)(row * BSTR + seg * 4) * 4,
                     src + (size_t)row * HWn + seg * 4);
            }
        }
        CP_COMMIT();
        CP_WAIT0();
        __syncthreads();

#pragma unroll
        for (int ks = 0; ks < 4; ks++) {
            int k2 = ks * 8 + (lane & 3);
            int rb = (mq * 16 + (lane >> 2)) * ASTR2 + ch * 32;
            u32 A0 = a2[rb + k2];
            u32 A1 = a2[rb + 8 * ASTR2 + k2];
            u32 A2r = a2[rb + k2 + 4];
            u32 A3 = a2[rb + 8 * ASTR2 + k2 + 4];
            int nb = pq * 64 + (lane >> 2);
#pragma unroll
            for (int nt = 0; nt < 8; nt++) {
                int n = nb + nt * 8;
                u32 b0 = bb[k2 * BSTR + n];
                u32 b1 = bb[(k2 + 4) * BSTR + n];
                mma_fp16(acc[nt], A0, A1, A2r, A3, b0, b1);
            }
        }
    }

    // store
    int oc = mq * 16 + (lane >> 2);
#pragma unroll
    for (int nt = 0; nt < 8; nt++) {
        int p = px0 + pq * 64 + nt * 8 + (lane & 3) * 2;
#pragma unroll
        for (int hf = 0; hf < 2; hf++) {
            float2 v = make_float2(acc[nt][hf * 2 + 0], acc[nt][hf * 2 + 1]);
            *(float2*)(out + ((size_t)b * 64 + oc + hf * 8) * HWn + p) = v;
        }
    }
}

// ============================================================
// launch
// ============================================================
extern "C" void kernel_launch(void* const* d_in, const int* in_sizes, int n_in,
                              void* d_out, int out_size)
{
    const float* x      = (const float*)d_in[0];
    const float* ref    = (const float*)d_in[1];
    const float* w_cd   = (const float*)d_in[2];
    const float* b_cd   = (const float*)d_in[3];
    const float* w_p    = (const float*)d_in[4];
    const float* b_p    = (const float*)d_in[5];
    const float* w_m    = (const float*)d_in[6];
    const float* b_m    = (const float*)d_in[7];
    const float* w_c    = (const float*)d_in[8];
    const float* b_c    = (const float*)d_in[9];
    const float* w_conv = (const float*)d_in[10];
    float* out = (float*)d_out;

    (void)in_sizes; (void)n_in; (void)out_size;

    size_t smem2 = (size_t)(576 * 28) * sizeof(float);   // 64512 B
    cudaFuncSetAttribute(k_offmod, cudaFuncAttributeMaxDynamicSharedMemorySize, (int)smem2);
    cudaFuncSetAttribute(k_conv,   cudaFuncAttributeMaxDynamicSharedMemorySize, SMEM_CONV_BYTES);
    cudaFuncSetAttribute(k_gemm2,  cudaFuncAttributeMaxDynamicSharedMemorySize, SMEM_G2_BYTES);

    int prep_elems = 9 * 64 * 288 + 64 * 288;
    k_prep<<<(prep_elems + 255) / 256, 256>>>(w_c, w_conv);
    k_fused<<<(Bn * HWn) / 256, 256>>>(x, ref, w_cd, b_cd);

    dim3 grid(Wn / TW, Hn / TH, Bn);   // (4, 16, 4)
    k_offmod<<<grid, 256, smem2>>>(w_p, b_p, w_m, b_m);
    k_conv<<<grid, NT, SMEM_CONV_BYTES>>>(x, b_c);

    dim3 grid2(HWn / 256, 1, Bn);      // (64, 1, 4)
    k_gemm2<<<grid2, 512, SMEM_G2_BYTES>>>(out);
}